// round 9
// baseline (speedup 1.0000x reference)
#include <cuda_runtime.h>
#include <cstdint>

#define H_  16
#define HS_ 64
#define C_  1024
#define T_  2048
#define B_  2
#define BT_ (B_ * T_)   // 4096
#define LOG2E 1.4426950408889634f

// ---------------------------------------------------------------------------
// Scratch (no device allocation allowed)
// ---------------------------------------------------------------------------
__device__ float g_q[B_ * H_ * T_ * HS_];
__device__ float g_k[B_ * H_ * T_ * HS_];
__device__ float g_v[B_ * H_ * T_ * HS_];
__device__ float g_att[BT_ * C_];
__device__ float g_bt[3 * H_ * HS_ * C_];   // K-major QKV weights: [3072][1024]
__device__ float g_wpt[C_ * C_];            // K-major Wp: [n][k]

// ---------------------------------------------------------------------------
__device__ __forceinline__ uint32_t f2tf32(float f) {
    uint32_t r;
    asm("cvt.rna.tf32.f32 %0, %1;" : "=r"(r) : "f"(f));
    return r;
}
__device__ __forceinline__ float ex2f(float x) {
    float y;
    asm("ex2.approx.f32 %0, %1;" : "=f"(y) : "f"(x));
    return y;
}
__device__ __forceinline__ void mma_tf32(float c[4], const uint32_t a[4],
                                         const uint32_t b[2]) {
    asm volatile(
        "mma.sync.aligned.m16n8k8.row.col.f32.tf32.tf32.f32 "
        "{%0,%1,%2,%3}, {%4,%5,%6,%7}, {%8,%9}, {%0,%1,%2,%3};"
        : "+f"(c[0]), "+f"(c[1]), "+f"(c[2]), "+f"(c[3])
        : "r"(a[0]), "r"(a[1]), "r"(a[2]), "r"(a[3]), "r"(b[0]), "r"(b[1]));
}

// ---------------------------------------------------------------------------
// Weight transposes into K-major scratch
// ---------------------------------------------------------------------------
__global__ void transpose_w(const float* __restrict__ Wq,
                            const float* __restrict__ Wk,
                            const float* __restrict__ Wv)
{
    __shared__ float tile[32][33];
    const int which = blockIdx.z >> 4;         // 0..2
    const int h     = blockIdx.z & 15;
    const float* W  = (which == 0) ? Wq : (which == 1) ? Wk : Wv;
    const int c0 = blockIdx.x * 32;
    const int d0 = blockIdx.y * 32;
    const int tx = threadIdx.x, ty = threadIdx.y;
#pragma unroll
    for (int j = 0; j < 32; j += 8)
        tile[ty + j][tx] = W[h * (C_ * HS_) + (c0 + ty + j) * HS_ + d0 + tx];
    __syncthreads();
    float* out = g_bt + (size_t)(which * 1024 + h * HS_ + d0) * C_ + c0;
#pragma unroll
    for (int j = 0; j < 32; j += 8)
        out[(ty + j) * C_ + tx] = tile[tx][ty + j];
}

__global__ void transpose_wp(const float* __restrict__ Wp)
{
    __shared__ float tile[32][33];
    const int k0 = blockIdx.x * 32;
    const int n0 = blockIdx.y * 32;
    const int tx = threadIdx.x, ty = threadIdx.y;
#pragma unroll
    for (int j = 0; j < 32; j += 8)
        tile[ty + j][tx] = Wp[(k0 + ty + j) * C_ + n0 + tx];
    __syncthreads();
#pragma unroll
    for (int j = 0; j < 32; j += 8)
        g_wpt[(size_t)(n0 + ty + j) * C_ + k0 + tx] = tile[tx][ty + j];
}

// ---------------------------------------------------------------------------
// tf32 mma.sync GEMM mainloop: 128x128 tile, K in 32-chunks, DOUBLE-BUFFERED
// SMEM (one barrier per chunk; staging STS overlaps next chunk's MMAs).
// ---------------------------------------------------------------------------
#define GEMM_SMEM_BYTES (4 * 128 * 36 * 4)   // As0,As1,Bs0,Bs1

__device__ __forceinline__ void gemm_core(
    const float* __restrict__ A, const float* __restrict__ Bt,
    int m0, int n0, float acc[4][4][4], uint32_t* gsm)
{
    uint32_t (*As[2])[36] = {(uint32_t(*)[36])gsm,
                             (uint32_t(*)[36])(gsm + 128 * 36)};
    uint32_t (*Bs[2])[36] = {(uint32_t(*)[36])(gsm + 2 * 128 * 36),
                             (uint32_t(*)[36])(gsm + 3 * 128 * 36)};

    const int tid  = threadIdx.x;
    const int wid  = tid >> 5;
    const int lane = tid & 31;
    const int wm = (wid & 1) * 64;
    const int wn = (wid >> 1) * 32;
    const int g  = lane >> 2;
    const int t4 = lane & 3;

    const int lrow = tid >> 3;        // 0..31, + p*32
    const int lc4  = (tid & 7) * 4;   // k-col (floats)

    const float* Ap = A + (size_t)(m0 + lrow) * C_ + lc4;
    const float* Bp = Bt + (size_t)(n0 + lrow) * C_ + lc4;

#pragma unroll
    for (int mt = 0; mt < 4; mt++)
#pragma unroll
        for (int nt = 0; nt < 4; nt++)
#pragma unroll
            for (int i = 0; i < 4; i++) acc[mt][nt][i] = 0.f;

    float4 ra[4], rb[4];
#pragma unroll
    for (int p = 0; p < 4; p++) {
        ra[p] = *(const float4*)(Ap + (size_t)p * 32 * C_);
        rb[p] = *(const float4*)(Bp + (size_t)p * 32 * C_);
    }
#pragma unroll
    for (int p = 0; p < 4; p++) {
        uint4 ta = {f2tf32(ra[p].x), f2tf32(ra[p].y),
                    f2tf32(ra[p].z), f2tf32(ra[p].w)};
        *(uint4*)&As[0][lrow + p * 32][lc4] = ta;
        uint4 tb = {f2tf32(rb[p].x), f2tf32(rb[p].y),
                    f2tf32(rb[p].z), f2tf32(rb[p].w)};
        *(uint4*)&Bs[0][lrow + p * 32][lc4] = tb;
    }
    __syncthreads();

#pragma unroll 1
    for (int it = 0; it < 32; ++it) {
        const int cur = it & 1, nxt = cur ^ 1;
        if (it < 31) {   // LDG for next chunk; completes during MMAs below
            const int kn = (it + 1) * 32;
#pragma unroll
            for (int p = 0; p < 4; p++) {
                ra[p] = *(const float4*)(Ap + kn + (size_t)p * 32 * C_);
                rb[p] = *(const float4*)(Bp + kn + (size_t)p * 32 * C_);
            }
        }

#pragma unroll
        for (int ks = 0; ks < 4; ks++) {
            const int k = ks * 8;
            uint32_t af[4][4], bf[4][2];
#pragma unroll
            for (int mt = 0; mt < 4; mt++) {
                const int r = wm + mt * 16 + g;
                af[mt][0] = As[cur][r][k + t4];
                af[mt][1] = As[cur][r + 8][k + t4];
                af[mt][2] = As[cur][r][k + t4 + 4];
                af[mt][3] = As[cur][r + 8][k + t4 + 4];
            }
#pragma unroll
            for (int nt = 0; nt < 4; nt++) {
                const int n = wn + nt * 8 + g;
                bf[nt][0] = Bs[cur][n][k + t4];
                bf[nt][1] = Bs[cur][n][k + t4 + 4];
            }
#pragma unroll
            for (int mt = 0; mt < 4; mt++)
#pragma unroll
                for (int nt = 0; nt < 4; nt++)
                    mma_tf32(acc[mt][nt], af[mt], bf[nt]);
        }

        if (it < 31) {   // store next chunk into the other buffer
#pragma unroll
            for (int p = 0; p < 4; p++) {
                uint4 ta = {f2tf32(ra[p].x), f2tf32(ra[p].y),
                            f2tf32(ra[p].z), f2tf32(ra[p].w)};
                *(uint4*)&As[nxt][lrow + p * 32][lc4] = ta;
                uint4 tb = {f2tf32(rb[p].x), f2tf32(rb[p].y),
                            f2tf32(rb[p].z), f2tf32(rb[p].w)};
                *(uint4*)&Bs[nxt][lrow + p * 32][lc4] = tb;
            }
        }
        __syncthreads();
    }
}

// ---------------------------------------------------------------------------
// QKV projection: M=4096 (b,t), N=3072 (qkv,h,d), K=1024
// ---------------------------------------------------------------------------
__global__ __launch_bounds__(256) void qkv_gemm_mma(const float* __restrict__ x)
{
    extern __shared__ uint32_t gsm[];
    const int m0 = blockIdx.y * 128;
    const int n0 = blockIdx.x * 128;

    float acc[4][4][4];
    gemm_core(x, g_bt, m0, n0, acc, gsm);

    const int tid  = threadIdx.x;
    const int wid  = tid >> 5;
    const int lane = tid & 31;
    const int wm = (wid & 1) * 64;
    const int wn = (wid >> 1) * 32;
    const int g  = lane >> 2;
    const int t4 = lane & 3;

#pragma unroll
    for (int mt = 0; mt < 4; mt++) {
#pragma unroll
        for (int nt = 0; nt < 4; nt++) {
            const int n  = n0 + wn + nt * 8 + t4 * 2;
            const int qk = n >> 10;
            const int h2 = (n >> 6) & (H_ - 1);
            const int d2 = n & (HS_ - 1);
            float* base = ((qk == 0) ? g_q : (qk == 1) ? g_k : g_v);
#pragma unroll
            for (int half = 0; half < 2; half++) {
                const int m = m0 + wm + mt * 16 + g + half * 8;
                const int b = m >> 11;
                const int t = m & (T_ - 1);
                float2 v;
                v.x = acc[mt][nt][half * 2 + 0];
                v.y = acc[mt][nt][half * 2 + 1];
                *(float2*)&base[(((size_t)b * H_ + h2) * T_ + t) * HS_ + d2] = v;
            }
        }
    }
}

// ---------------------------------------------------------------------------
// Output projection: M=4096, N=1024, K=1024, + bias
// ---------------------------------------------------------------------------
__global__ __launch_bounds__(256) void out_gemm_mma(const float* __restrict__ bp,
                                                    float* __restrict__ out)
{
    extern __shared__ uint32_t gsm[];
    const int m0 = blockIdx.y * 128;
    const int n0 = blockIdx.x * 128;

    float acc[4][4][4];
    gemm_core(g_att, g_wpt, m0, n0, acc, gsm);

    const int tid  = threadIdx.x;
    const int wid  = tid >> 5;
    const int lane = tid & 31;
    const int wm = (wid & 1) * 64;
    const int wn = (wid >> 1) * 32;
    const int g  = lane >> 2;
    const int t4 = lane & 3;

#pragma unroll
    for (int mt = 0; mt < 4; mt++) {
#pragma unroll
        for (int nt = 0; nt < 4; nt++) {
            const int n = n0 + wn + nt * 8 + t4 * 2;
            const float2 bias = *(const float2*)(bp + n);
#pragma unroll
            for (int half = 0; half < 2; half++) {
                const int m = m0 + wm + mt * 16 + g + half * 8;
                float2 v;
                v.x = acc[mt][nt][half * 2 + 0] + bias.x;
                v.y = acc[mt][nt][half * 2 + 1] + bias.y;
                *(float2*)&out[(size_t)m * C_ + n] = v;
            }
        }
    }
}

// ---------------------------------------------------------------------------
// Flash attention, tf32 mma.sync. One block = 128 q rows of one (b,h).
// 8 warps; warp w owns rows [w*16, w*16+16). KV tiles of 64 keys; next tile's
// K/V prefetched into registers during current tile's compute. P stays in
// registers (C-frag -> A-frag shuffle). Fully-masked warp-tiles skip compute.
// ---------------------------------------------------------------------------
__global__ __launch_bounds__(256) void flash_mma()
{
    __shared__ uint32_t Ks[64 * 68];
    __shared__ uint32_t Vs[64 * 72];

    const int qt  = gridDim.x - 1 - blockIdx.x;   // long blocks first
    const int bh  = blockIdx.y;
    const int tid = threadIdx.x;
    const int wid = tid >> 5, lane = tid & 31;
    const int g = lane >> 2, t4 = lane & 3;
    const int wr = wid * 16;
    const int q0 = qt * 128;

    const float* qb = g_q + (size_t)bh * T_ * HS_;
    const float* kb = g_k + (size_t)bh * T_ * HS_;
    const float* vb = g_v + (size_t)bh * T_ * HS_;

    // --- stage Q through Vs in two 64-row passes; extract qa fragments ---
    const float qscale = 0.125f * LOG2E;
    uint32_t qa[8][4];
#pragma unroll
    for (int pass = 0; pass < 2; pass++) {
#pragma unroll
        for (int it = 0; it < 4; it++) {
            int l = it * 256 + tid, r = l >> 4, c4 = (l & 15) * 4;
            float4 v = *(const float4*)(qb + (size_t)(q0 + pass * 64 + r) * HS_ + c4);
            uint32_t* d = &Vs[r * 72 + c4];
            d[0] = f2tf32(v.x * qscale); d[1] = f2tf32(v.y * qscale);
            d[2] = f2tf32(v.z * qscale); d[3] = f2tf32(v.w * qscale);
        }
        __syncthreads();
        if ((wid >> 2) == pass) {
            const int lr = wr + g - pass * 64;
#pragma unroll
            for (int kk = 0; kk < 8; kk++) {
                qa[kk][0] = Vs[lr * 72 + t4 + 8 * kk];
                qa[kk][1] = Vs[(lr + 8) * 72 + t4 + 8 * kk];
                qa[kk][2] = Vs[lr * 72 + t4 + 4 + 8 * kk];
                qa[kk][3] = Vs[(lr + 8) * 72 + t4 + 4 + 8 * kk];
            }
        }
        __syncthreads();
    }

    float oacc[8][4];
#pragma unroll
    for (int nt = 0; nt < 8; nt++)
#pragma unroll
        for (int i = 0; i < 4; i++) oacc[nt][i] = 0.f;
    float m0 = -1e30f, m1 = -1e30f, l0 = 0.f, l1 = 0.f;

    // P shuffle mapping: P[g][t4+8kk] lives in lane g*4+(t4>>1), comp t4&1
    const int src0 = g * 4 + (t4 >> 1);
    const int src2 = src0 + 2;
    const bool sel = (t4 & 1) != 0;

    // per-thread staging coords (64 rows x 16 float4 / 256 thr = 4 each)
    const int srow = tid >> 4;          // 0..15, +it*16
    const int sc4  = (tid & 15) * 4;

    const int nkt = 2 * qt + 2;

    // prefetch tile 0
    float4 rk[4], rv[4];
#pragma unroll
    for (int it = 0; it < 4; it++) {
        const int r = srow + it * 16;
        rk[it] = *(const float4*)(kb + (size_t)r * HS_ + sc4);
        rv[it] = *(const float4*)(vb + (size_t)r * HS_ + sc4);
    }

#pragma unroll 1
    for (int kt = 0; kt < nkt; kt++) {
        const int k0 = kt * 64;
        __syncthreads();   // prior tile's Ks/Vs reads (and qa extraction) done
#pragma unroll
        for (int it = 0; it < 4; it++) {
            const int r = srow + it * 16;
            uint32_t* dk = &Ks[r * 68 + sc4];
            dk[0] = f2tf32(rk[it].x); dk[1] = f2tf32(rk[it].y);
            dk[2] = f2tf32(rk[it].z); dk[3] = f2tf32(rk[it].w);
            uint32_t* dv = &Vs[r * 72 + sc4];
            dv[0] = f2tf32(rv[it].x); dv[1] = f2tf32(rv[it].y);
            dv[2] = f2tf32(rv[it].z); dv[3] = f2tf32(rv[it].w);
        }
        __syncthreads();

        if (kt + 1 < nkt) {   // prefetch next tile; overlaps compute below
            const int kn = (kt + 1) * 64;
#pragma unroll
            for (int it = 0; it < 4; it++) {
                const int r = kn + srow + it * 16;
                rk[it] = *(const float4*)(kb + (size_t)r * HS_ + sc4);
                rv[it] = *(const float4*)(vb + (size_t)r * HS_ + sc4);
            }
        }

        // warp-uniform skip: tile entirely above this warp's diagonal
        if (k0 > q0 + wr + 15) continue;

        // S = Q K^T  (units: log2)
        float sacc[8][4];
#pragma unroll
        for (int nt = 0; nt < 8; nt++)
#pragma unroll
            for (int i = 0; i < 4; i++) sacc[nt][i] = 0.f;
#pragma unroll
        for (int kk = 0; kk < 8; kk++) {
#pragma unroll
            for (int nt = 0; nt < 8; nt++) {
                uint32_t bf[2];
                bf[0] = Ks[(g + 8 * nt) * 68 + t4 + 8 * kk];
                bf[1] = Ks[(g + 8 * nt) * 68 + t4 + 4 + 8 * kk];
                mma_tf32(sacc[nt], qa[kk], bf);
            }
        }

        if (k0 + 63 > q0 + wr) {   // tile overlaps diagonal for this warp
            const int r0 = q0 + wr + g, r1 = r0 + 8;
#pragma unroll
            for (int nt = 0; nt < 8; nt++) {
                const int c = k0 + 8 * nt + 2 * t4;
                if (c     > r0) sacc[nt][0] = -1e30f;
                if (c + 1 > r0) sacc[nt][1] = -1e30f;
                if (c     > r1) sacc[nt][2] = -1e30f;
                if (c + 1 > r1) sacc[nt][3] = -1e30f;
            }
        }

        // online softmax (base 2)
        float ml0 = -1e30f, ml1 = -1e30f;
#pragma unroll
        for (int nt = 0; nt < 8; nt++) {
            ml0 = fmaxf(ml0, fmaxf(sacc[nt][0], sacc[nt][1]));
            ml1 = fmaxf(ml1, fmaxf(sacc[nt][2], sacc[nt][3]));
        }
        ml0 = fmaxf(ml0, __shfl_xor_sync(0xffffffffu, ml0, 1));
        ml0 = fmaxf(ml0, __shfl_xor_sync(0xffffffffu, ml0, 2));
        ml1 = fmaxf(ml1, __shfl_xor_sync(0xffffffffu, ml1, 1));
        ml1 = fmaxf(ml1, __shfl_xor_sync(0xffffffffu, ml1, 2));
        const float mn0 = fmaxf(m0, ml0), mn1 = fmaxf(m1, ml1);
        const float corr0 = ex2f(m0 - mn0), corr1 = ex2f(m1 - mn1);
        m0 = mn0; m1 = mn1;

        uint32_t pu[8][4];
        float ps0 = 0.f, ps1 = 0.f;
#pragma unroll
        for (int nt = 0; nt < 8; nt++) {
            float p00 = ex2f(sacc[nt][0] - mn0);
            float p01 = ex2f(sacc[nt][1] - mn0);
            float p10 = ex2f(sacc[nt][2] - mn1);
            float p11 = ex2f(sacc[nt][3] - mn1);
            ps0 += p00 + p01;
            ps1 += p10 + p11;
            pu[nt][0] = f2tf32(p00); pu[nt][1] = f2tf32(p01);
            pu[nt][2] = f2tf32(p10); pu[nt][3] = f2tf32(p11);
            oacc[nt][0] *= corr0; oacc[nt][1] *= corr0;
            oacc[nt][2] *= corr1; oacc[nt][3] *= corr1;
        }
        ps0 += __shfl_xor_sync(0xffffffffu, ps0, 1);
        ps0 += __shfl_xor_sync(0xffffffffu, ps0, 2);
        ps1 += __shfl_xor_sync(0xffffffffu, ps1, 1);
        ps1 += __shfl_xor_sync(0xffffffffu, ps1, 2);
        l0 = l0 * corr0 + ps0;
        l1 = l1 * corr1 + ps1;

        // O += P V  (P redistributed C-frag -> A-frag via shuffles)
#pragma unroll
        for (int kk = 0; kk < 8; kk++) {
            uint32_t pa[4];
            uint32_t v0 = __shfl_sync(0xffffffffu, pu[kk][0], src0);
            uint32_t v1 = __shfl_sync(0xffffffffu, pu[kk][1], src0);
            uint32_t v2 = __shfl_sync(0xffffffffu, pu[kk][2], src0);
            uint32_t v3 = __shfl_sync(0xffffffffu, pu[kk][3], src0);
            pa[0] = sel ? v1 : v0;    // P[g][t4+8kk]
            pa[1] = sel ? v3 : v2;    // P[g+8][t4+8kk]
            uint32_t w0 = __shfl_sync(0xffffffffu, pu[kk][0], src2);
            uint32_t w1 = __shfl_sync(0xffffffffu, pu[kk][1], src2);
            uint32_t w2 = __shfl_sync(0xffffffffu, pu[kk][2], src2);
            uint32_t w3 = __shfl_sync(0xffffffffu, pu[kk][3], src2);
            pa[2] = sel ? w1 : w0;    // P[g][t4+4+8kk]
            pa[3] = sel ? w3 : w2;    // P[g+8][t4+4+8kk]
#pragma unroll
            for (int nt = 0; nt < 8; nt++) {
                uint32_t bf[2];
                bf[0] = Vs[(t4 + 8 * kk) * 72 + g + 8 * nt];
                bf[1] = Vs[(t4 + 4 + 8 * kk) * 72 + g + 8 * nt];
                mma_tf32(oacc[nt], pa, bf);
            }
        }
    }

    // epilogue: normalize and write g_att[b, t, h*64 + hs]
    const float inv0 = 1.0f / l0, inv1 = 1.0f / l1;
    const int b = bh >> 4;
    const int h = bh & (H_ - 1);
    const int qrow0 = q0 + wr + g;
    const int qrow1 = qrow0 + 8;
    float* dst0 = g_att + ((size_t)b * T_ + qrow0) * C_ + h * HS_;
    float* dst1 = g_att + ((size_t)b * T_ + qrow1) * C_ + h * HS_;
#pragma unroll
    for (int nt = 0; nt < 8; nt++) {
        float2 v0 = {oacc[nt][0] * inv0, oacc[nt][1] * inv0};
        *(float2*)&dst0[8 * nt + 2 * t4] = v0;
        float2 v1 = {oacc[nt][2] * inv1, oacc[nt][3] * inv1};
        *(float2*)&dst1[8 * nt + 2 * t4] = v1;
    }
}

// ---------------------------------------------------------------------------
extern "C" void kernel_launch(void* const* d_in, const int* in_sizes, int n_in,
                              void* d_out, int out_size)
{
    const float* x  = (const float*)d_in[0];
    const float* Wq = (const float*)d_in[1];
    const float* Wk = (const float*)d_in[2];
    const float* Wv = (const float*)d_in[3];
    const float* Wp = (const float*)d_in[4];
    const float* bp = (const float*)d_in[5];
    float* out = (float*)d_out;

    cudaFuncSetAttribute(qkv_gemm_mma, cudaFuncAttributeMaxDynamicSharedMemorySize,
                         GEMM_SMEM_BYTES);
    cudaFuncSetAttribute(out_gemm_mma, cudaFuncAttributeMaxDynamicSharedMemorySize,
                         GEMM_SMEM_BYTES);

    // 0) weight transposes into K-major scratch
    transpose_w<<<dim3(C_ / 32, HS_ / 32, 3 * H_), dim3(32, 8)>>>(Wq, Wk, Wv);
    transpose_wp<<<dim3(C_ / 32, C_ / 32), dim3(32, 8)>>>(Wp);
    // 1) QKV projection (tensor, tf32, double-buffered): M=4096, N=3072
    qkv_gemm_mma<<<dim3(3072 / 128, BT_ / 128), 256, GEMM_SMEM_BYTES>>>(x);
    // 2) Causal flash attention (tensor, tf32, 128-row blocks, prefetch)
    flash_mma<<<dim3(T_ / 128, B_ * H_), 256>>>();
    // 3) Output projection + bias (tensor, tf32, double-buffered): M=4096, N=1024
    out_gemm_mma<<<dim3(C_ / 128, BT_ / 128), 256, GEMM_SMEM_BYTES>>>(bp, out);
}

// round 10
// speedup vs baseline: 1.0649x; 1.0649x over previous
#include <cuda_runtime.h>
#include <cstdint>

#define H_  16
#define HS_ 64
#define C_  1024
#define T_  2048
#define B_  2
#define BT_ (B_ * T_)   // 4096
#define LOG2E 1.4426950408889634f

// ---------------------------------------------------------------------------
// Scratch (no device allocation allowed)
// ---------------------------------------------------------------------------
__device__ float    g_q[B_ * H_ * T_ * HS_];
__device__ float    g_k[B_ * H_ * T_ * HS_];
__device__ float    g_v[B_ * H_ * T_ * HS_];
__device__ uint32_t g_att[BT_ * C_];            // tf32 bits (flash epilogue)
__device__ uint32_t g_xt[BT_ * C_];             // tf32 bits of x
__device__ uint32_t g_bt[3 * H_ * HS_ * C_];    // tf32 K-major QKV weights
__device__ uint32_t g_wpt[C_ * C_];             // tf32 K-major Wp

// ---------------------------------------------------------------------------
__device__ __forceinline__ uint32_t f2tf32(float f) {
    uint32_t r;
    asm("cvt.rna.tf32.f32 %0, %1;" : "=r"(r) : "f"(f));
    return r;
}
__device__ __forceinline__ float ex2f(float x) {
    float y;
    asm("ex2.approx.f32 %0, %1;" : "=f"(y) : "f"(x));
    return y;
}
__device__ __forceinline__ void mma_tf32(float c[4], const uint32_t a[4],
                                         const uint32_t b[2]) {
    asm volatile(
        "mma.sync.aligned.m16n8k8.row.col.f32.tf32.tf32.f32 "
        "{%0,%1,%2,%3}, {%4,%5,%6,%7}, {%8,%9}, {%0,%1,%2,%3};"
        : "+f"(c[0]), "+f"(c[1]), "+f"(c[2]), "+f"(c[3])
        : "r"(a[0]), "r"(a[1]), "r"(a[2]), "r"(a[3]), "r"(b[0]), "r"(b[1]));
}
__device__ __forceinline__ void cp_async16(void* dst, const void* src) {
    uint32_t d = (uint32_t)__cvta_generic_to_shared(dst);
    asm volatile("cp.async.cg.shared.global [%0], [%1], 16;"
                 :: "r"(d), "l"(src) : "memory");
}

// ---------------------------------------------------------------------------
// One-time input conversion: x -> tf32 bits
// ---------------------------------------------------------------------------
__global__ void convert_x(const float* __restrict__ x)
{
    const int i = (blockIdx.x * 256 + threadIdx.x) * 4;
    float4 v = *(const float4*)(x + i);
    uint4 t = {f2tf32(v.x), f2tf32(v.y), f2tf32(v.z), f2tf32(v.w)};
    *(uint4*)(g_xt + i) = t;
}

// ---------------------------------------------------------------------------
// Weight transposes into K-major tf32 scratch
// ---------------------------------------------------------------------------
__global__ void transpose_w(const float* __restrict__ Wq,
                            const float* __restrict__ Wk,
                            const float* __restrict__ Wv)
{
    __shared__ float tile[32][33];
    const int which = blockIdx.z >> 4;         // 0..2
    const int h     = blockIdx.z & 15;
    const float* W  = (which == 0) ? Wq : (which == 1) ? Wk : Wv;
    const int c0 = blockIdx.x * 32;
    const int d0 = blockIdx.y * 32;
    const int tx = threadIdx.x, ty = threadIdx.y;
#pragma unroll
    for (int j = 0; j < 32; j += 8)
        tile[ty + j][tx] = W[h * (C_ * HS_) + (c0 + ty + j) * HS_ + d0 + tx];
    __syncthreads();
    uint32_t* out = g_bt + (size_t)(which * 1024 + h * HS_ + d0) * C_ + c0;
#pragma unroll
    for (int j = 0; j < 32; j += 8)
        out[(ty + j) * C_ + tx] = f2tf32(tile[tx][ty + j]);
}

__global__ void transpose_wp(const float* __restrict__ Wp)
{
    __shared__ float tile[32][33];
    const int k0 = blockIdx.x * 32;
    const int n0 = blockIdx.y * 32;
    const int tx = threadIdx.x, ty = threadIdx.y;
#pragma unroll
    for (int j = 0; j < 32; j += 8)
        tile[ty + j][tx] = Wp[(k0 + ty + j) * C_ + n0 + tx];
    __syncthreads();
#pragma unroll
    for (int j = 0; j < 32; j += 8)
        g_wpt[(size_t)(n0 + ty + j) * C_ + k0 + tx] = f2tf32(tile[tx][ty + j]);
}

// ---------------------------------------------------------------------------
// tf32 mma.sync GEMM mainloop: 128x128 tile, K in 32-chunks, 4-stage cp.async
// pipeline. Operands are pre-converted tf32 bits; no cvt/LDG/STS in the loop.
// ---------------------------------------------------------------------------
#define NSTAGE   4
#define STG_U32  (2 * 128 * 36)
#define GEMM_SMEM_BYTES (NSTAGE * STG_U32 * 4)   // 147456

__device__ __forceinline__ void gemm_issue(uint32_t* gsm, int s,
                                           const uint32_t* Ap,
                                           const uint32_t* Bp,
                                           int k0, int lrow, int lc4)
{
    uint32_t* As = gsm + s * STG_U32;
    uint32_t* Bs = As + 128 * 36;
#pragma unroll
    for (int p = 0; p < 4; p++) {
        cp_async16(&As[(lrow + p * 32) * 36 + lc4], Ap + k0 + (size_t)p * 32 * C_);
        cp_async16(&Bs[(lrow + p * 32) * 36 + lc4], Bp + k0 + (size_t)p * 32 * C_);
    }
    asm volatile("cp.async.commit_group;" ::: "memory");
}

__device__ __forceinline__ void gemm_core(
    const uint32_t* __restrict__ A, const uint32_t* __restrict__ Bt,
    int m0, int n0, float acc[4][4][4], uint32_t* gsm)
{
    const int tid  = threadIdx.x;
    const int wid  = tid >> 5;
    const int lane = tid & 31;
    const int wm = (wid & 1) * 64;
    const int wn = (wid >> 1) * 32;
    const int g  = lane >> 2;
    const int t4 = lane & 3;

    const int lrow = tid >> 3;        // 0..31, + p*32
    const int lc4  = (tid & 7) * 4;   // k-col (u32)

    const uint32_t* Ap = A + (size_t)(m0 + lrow) * C_ + lc4;
    const uint32_t* Bp = Bt + (size_t)(n0 + lrow) * C_ + lc4;

#pragma unroll
    for (int mt = 0; mt < 4; mt++)
#pragma unroll
        for (int nt = 0; nt < 4; nt++)
#pragma unroll
            for (int i = 0; i < 4; i++) acc[mt][nt][i] = 0.f;

    gemm_issue(gsm, 0, Ap, Bp, 0,  lrow, lc4);
    gemm_issue(gsm, 1, Ap, Bp, 32, lrow, lc4);
    gemm_issue(gsm, 2, Ap, Bp, 64, lrow, lc4);

#pragma unroll 1
    for (int it = 0; it < 32; ++it) {
        if (it < 30)       asm volatile("cp.async.wait_group 2;" ::: "memory");
        else if (it == 30) asm volatile("cp.async.wait_group 1;" ::: "memory");
        else               asm volatile("cp.async.wait_group 0;" ::: "memory");
        __syncthreads();   // chunk `it` visible; buffer (it+3)%4 free

        if (it + 3 < 32)
            gemm_issue(gsm, (it + 3) & 3, Ap, Bp, (it + 3) * 32, lrow, lc4);

        const uint32_t* As = gsm + (it & 3) * STG_U32;
        const uint32_t* Bs = As + 128 * 36;
#pragma unroll
        for (int ks = 0; ks < 4; ks++) {
            const int k = ks * 8;
            uint32_t af[4][4], bf[4][2];
#pragma unroll
            for (int mt = 0; mt < 4; mt++) {
                const int r = wm + mt * 16 + g;
                af[mt][0] = As[r * 36 + k + t4];
                af[mt][1] = As[(r + 8) * 36 + k + t4];
                af[mt][2] = As[r * 36 + k + t4 + 4];
                af[mt][3] = As[(r + 8) * 36 + k + t4 + 4];
            }
#pragma unroll
            for (int nt = 0; nt < 4; nt++) {
                const int n = wn + nt * 8 + g;
                bf[nt][0] = Bs[n * 36 + k + t4];
                bf[nt][1] = Bs[n * 36 + k + t4 + 4];
            }
#pragma unroll
            for (int mt = 0; mt < 4; mt++)
#pragma unroll
                for (int nt = 0; nt < 4; nt++)
                    mma_tf32(acc[mt][nt], af[mt], bf[nt]);
        }
    }
}

// ---------------------------------------------------------------------------
// QKV projection: M=4096 (b,t), N=3072 (qkv,h,d), K=1024
// ---------------------------------------------------------------------------
__global__ __launch_bounds__(256) void qkv_gemm_mma()
{
    extern __shared__ uint32_t gsm[];
    const int m0 = blockIdx.y * 128;
    const int n0 = blockIdx.x * 128;

    float acc[4][4][4];
    gemm_core(g_xt, g_bt, m0, n0, acc, gsm);

    const int tid  = threadIdx.x;
    const int wid  = tid >> 5;
    const int lane = tid & 31;
    const int wm = (wid & 1) * 64;
    const int wn = (wid >> 1) * 32;
    const int g  = lane >> 2;
    const int t4 = lane & 3;

#pragma unroll
    for (int mt = 0; mt < 4; mt++) {
#pragma unroll
        for (int nt = 0; nt < 4; nt++) {
            const int n  = n0 + wn + nt * 8 + t4 * 2;
            const int qk = n >> 10;
            const int h2 = (n >> 6) & (H_ - 1);
            const int d2 = n & (HS_ - 1);
            float* base = ((qk == 0) ? g_q : (qk == 1) ? g_k : g_v);
#pragma unroll
            for (int half = 0; half < 2; half++) {
                const int m = m0 + wm + mt * 16 + g + half * 8;
                const int b = m >> 11;
                const int t = m & (T_ - 1);
                float2 v;
                v.x = acc[mt][nt][half * 2 + 0];
                v.y = acc[mt][nt][half * 2 + 1];
                *(float2*)&base[(((size_t)b * H_ + h2) * T_ + t) * HS_ + d2] = v;
            }
        }
    }
}

// ---------------------------------------------------------------------------
// Output projection: M=4096, N=1024, K=1024, + bias
// ---------------------------------------------------------------------------
__global__ __launch_bounds__(256) void out_gemm_mma(const float* __restrict__ bp,
                                                    float* __restrict__ out)
{
    extern __shared__ uint32_t gsm[];
    const int m0 = blockIdx.y * 128;
    const int n0 = blockIdx.x * 128;

    float acc[4][4][4];
    gemm_core(g_att, g_wpt, m0, n0, acc, gsm);

    const int tid  = threadIdx.x;
    const int wid  = tid >> 5;
    const int lane = tid & 31;
    const int wm = (wid & 1) * 64;
    const int wn = (wid >> 1) * 32;
    const int g  = lane >> 2;
    const int t4 = lane & 3;

#pragma unroll
    for (int mt = 0; mt < 4; mt++) {
#pragma unroll
        for (int nt = 0; nt < 4; nt++) {
            const int n = n0 + wn + nt * 8 + t4 * 2;
            const float2 bias = *(const float2*)(bp + n);
#pragma unroll
            for (int half = 0; half < 2; half++) {
                const int m = m0 + wm + mt * 16 + g + half * 8;
                float2 v;
                v.x = acc[mt][nt][half * 2 + 0] + bias.x;
                v.y = acc[mt][nt][half * 2 + 1] + bias.y;
                *(float2*)&out[(size_t)m * C_ + n] = v;
            }
        }
    }
}

// ---------------------------------------------------------------------------
// Flash attention (R7-proven 64-row version), tf32 mma.sync, register P.
// Epilogue writes g_att as tf32 bits (pre-converted for the output GEMM).
// ---------------------------------------------------------------------------
#define FA_SMEM_U32 (64 * 68 + 64 * 72)

__global__ __launch_bounds__(128, 3) void flash_mma()
{
    extern __shared__ uint32_t sm[];
    uint32_t* Ks = sm;                    // [64][68]
    uint32_t* Vs = sm + 64 * 68;          // [64][72]

    const int qt  = gridDim.x - 1 - blockIdx.x;   // long blocks first
    const int bh  = blockIdx.y;
    const int tid = threadIdx.x;
    const int wid = tid >> 5, lane = tid & 31;
    const int g = lane >> 2, t4 = lane & 3;
    const int wr = wid * 16;
    const int q0 = qt * 64;

    const float* qb = g_q + (size_t)bh * T_ * HS_;
    const float* kb = g_k + (size_t)bh * T_ * HS_;
    const float* vb = g_v + (size_t)bh * T_ * HS_;

    // stage Q through Ks (scale folded: 1/sqrt(HS) * log2(e)), tf32
    const float qscale = 0.125f * LOG2E;
#pragma unroll
    for (int it = 0; it < 8; it++) {
        int l = it * 128 + tid, r = l >> 4, c4 = (l & 15) * 4;
        float4 v = *(const float4*)(qb + (size_t)(q0 + r) * HS_ + c4);
        uint32_t* d = &Ks[r * 68 + c4];
        d[0] = f2tf32(v.x * qscale); d[1] = f2tf32(v.y * qscale);
        d[2] = f2tf32(v.z * qscale); d[3] = f2tf32(v.w * qscale);
    }
    __syncthreads();

    uint32_t qa[8][4];
#pragma unroll
    for (int kk = 0; kk < 8; kk++) {
        qa[kk][0] = Ks[(wr + g) * 68 + t4 + 8 * kk];
        qa[kk][1] = Ks[(wr + g + 8) * 68 + t4 + 8 * kk];
        qa[kk][2] = Ks[(wr + g) * 68 + t4 + 4 + 8 * kk];
        qa[kk][3] = Ks[(wr + g + 8) * 68 + t4 + 4 + 8 * kk];
    }

    float oacc[8][4];
#pragma unroll
    for (int nt = 0; nt < 8; nt++)
#pragma unroll
        for (int i = 0; i < 4; i++) oacc[nt][i] = 0.f;
    float m0 = -1e30f, m1 = -1e30f, l0 = 0.f, l1 = 0.f;

    // P shuffle mapping: P[g][t4+8kk] lives in lane g*4+(t4>>1), comp t4&1
    const int src0 = g * 4 + (t4 >> 1);
    const int src2 = src0 + 2;
    const bool sel = (t4 & 1) != 0;

#pragma unroll 1
    for (int kt = 0; kt <= qt; kt++) {
        const int k0 = kt * 64;
        __syncthreads();   // prior tile's Ks/Vs consumers (and qa reads) done
#pragma unroll
        for (int it = 0; it < 8; it++) {
            int l = it * 128 + tid, r = l >> 4, c4 = (l & 15) * 4;
            float4 kv = *(const float4*)(kb + (size_t)(k0 + r) * HS_ + c4);
            uint32_t* dk = &Ks[r * 68 + c4];
            dk[0] = f2tf32(kv.x); dk[1] = f2tf32(kv.y);
            dk[2] = f2tf32(kv.z); dk[3] = f2tf32(kv.w);
            float4 vv = *(const float4*)(vb + (size_t)(k0 + r) * HS_ + c4);
            uint32_t* dv = &Vs[r * 72 + c4];
            dv[0] = f2tf32(vv.x); dv[1] = f2tf32(vv.y);
            dv[2] = f2tf32(vv.z); dv[3] = f2tf32(vv.w);
        }
        __syncthreads();

        // S = Q K^T  (units: log2)
        float sacc[8][4];
#pragma unroll
        for (int nt = 0; nt < 8; nt++)
#pragma unroll
            for (int i = 0; i < 4; i++) sacc[nt][i] = 0.f;
#pragma unroll
        for (int kk = 0; kk < 8; kk++) {
#pragma unroll
            for (int nt = 0; nt < 8; nt++) {
                uint32_t bf[2];
                bf[0] = Ks[(g + 8 * nt) * 68 + t4 + 8 * kk];
                bf[1] = Ks[(g + 8 * nt) * 68 + t4 + 4 + 8 * kk];
                mma_tf32(sacc[nt], qa[kk], bf);
            }
        }

        if (kt == qt) {   // causal mask on the diagonal tile (local coords)
            const int r0 = wr + g, r1 = wr + g + 8;
#pragma unroll
            for (int nt = 0; nt < 8; nt++) {
                const int c = 8 * nt + 2 * t4;
                if (c     > r0) sacc[nt][0] = -1e30f;
                if (c + 1 > r0) sacc[nt][1] = -1e30f;
                if (c     > r1) sacc[nt][2] = -1e30f;
                if (c + 1 > r1) sacc[nt][3] = -1e30f;
            }
        }

        // online softmax (base 2)
        float ml0 = -1e30f, ml1 = -1e30f;
#pragma unroll
        for (int nt = 0; nt < 8; nt++) {
            ml0 = fmaxf(ml0, fmaxf(sacc[nt][0], sacc[nt][1]));
            ml1 = fmaxf(ml1, fmaxf(sacc[nt][2], sacc[nt][3]));
        }
        ml0 = fmaxf(ml0, __shfl_xor_sync(0xffffffffu, ml0, 1));
        ml0 = fmaxf(ml0, __shfl_xor_sync(0xffffffffu, ml0, 2));
        ml1 = fmaxf(ml1, __shfl_xor_sync(0xffffffffu, ml1, 1));
        ml1 = fmaxf(ml1, __shfl_xor_sync(0xffffffffu, ml1, 2));
        const float mn0 = fmaxf(m0, ml0), mn1 = fmaxf(m1, ml1);
        const float corr0 = ex2f(m0 - mn0), corr1 = ex2f(m1 - mn1);
        m0 = mn0; m1 = mn1;

        uint32_t pu[8][4];
        float ps0 = 0.f, ps1 = 0.f;
#pragma unroll
        for (int nt = 0; nt < 8; nt++) {
            float p00 = ex2f(sacc[nt][0] - mn0);
            float p01 = ex2f(sacc[nt][1] - mn0);
            float p10 = ex2f(sacc[nt][2] - mn1);
            float p11 = ex2f(sacc[nt][3] - mn1);
            ps0 += p00 + p01;
            ps1 += p10 + p11;
            pu[nt][0] = f2tf32(p00); pu[nt][1] = f2tf32(p01);
            pu[nt][2] = f2tf32(p10); pu[nt][3] = f2tf32(p11);
            oacc[nt][0] *= corr0; oacc[nt][1] *= corr0;
            oacc[nt][2] *= corr1; oacc[nt][3] *= corr1;
        }
        ps0 += __shfl_xor_sync(0xffffffffu, ps0, 1);
        ps0 += __shfl_xor_sync(0xffffffffu, ps0, 2);
        ps1 += __shfl_xor_sync(0xffffffffu, ps1, 1);
        ps1 += __shfl_xor_sync(0xffffffffu, ps1, 2);
        l0 = l0 * corr0 + ps0;
        l1 = l1 * corr1 + ps1;

        // O += P V  (P redistributed C-frag -> A-frag via shuffles)
#pragma unroll
        for (int kk = 0; kk < 8; kk++) {
            uint32_t pa[4];
            uint32_t v0 = __shfl_sync(0xffffffffu, pu[kk][0], src0);
            uint32_t v1 = __shfl_sync(0xffffffffu, pu[kk][1], src0);
            uint32_t v2 = __shfl_sync(0xffffffffu, pu[kk][2], src0);
            uint32_t v3 = __shfl_sync(0xffffffffu, pu[kk][3], src0);
            pa[0] = sel ? v1 : v0;    // P[g][t4+8kk]
            pa[1] = sel ? v3 : v2;    // P[g+8][t4+8kk]
            uint32_t w0 = __shfl_sync(0xffffffffu, pu[kk][0], src2);
            uint32_t w1 = __shfl_sync(0xffffffffu, pu[kk][1], src2);
            uint32_t w2 = __shfl_sync(0xffffffffu, pu[kk][2], src2);
            uint32_t w3 = __shfl_sync(0xffffffffu, pu[kk][3], src2);
            pa[2] = sel ? w1 : w0;    // P[g][t4+4+8kk]
            pa[3] = sel ? w3 : w2;    // P[g+8][t4+4+8kk]
#pragma unroll
            for (int nt = 0; nt < 8; nt++) {
                uint32_t bf[2];
                bf[0] = Vs[(t4 + 8 * kk) * 72 + g + 8 * nt];
                bf[1] = Vs[(t4 + 4 + 8 * kk) * 72 + g + 8 * nt];
                mma_tf32(oacc[nt], pa, bf);
            }
        }
    }

    // epilogue: normalize, convert to tf32 bits, write g_att[b, t, h*64 + hs]
    const float inv0 = 1.0f / l0, inv1 = 1.0f / l1;
    const int b = bh >> 4;
    const int h = bh & (H_ - 1);
    const int qrow0 = q0 + wr + g;
    const int qrow1 = qrow0 + 8;
    uint32_t* dst0 = g_att + ((size_t)b * T_ + qrow0) * C_ + h * HS_;
    uint32_t* dst1 = g_att + ((size_t)b * T_ + qrow1) * C_ + h * HS_;
#pragma unroll
    for (int nt = 0; nt < 8; nt++) {
        uint2 v0 = {f2tf32(oacc[nt][0] * inv0), f2tf32(oacc[nt][1] * inv0)};
        *(uint2*)&dst0[8 * nt + 2 * t4] = v0;
        uint2 v1 = {f2tf32(oacc[nt][2] * inv1), f2tf32(oacc[nt][3] * inv1)};
        *(uint2*)&dst1[8 * nt + 2 * t4] = v1;
    }
}

// ---------------------------------------------------------------------------
extern "C" void kernel_launch(void* const* d_in, const int* in_sizes, int n_in,
                              void* d_out, int out_size)
{
    const float* x  = (const float*)d_in[0];
    const float* Wq = (const float*)d_in[1];
    const float* Wk = (const float*)d_in[2];
    const float* Wv = (const float*)d_in[3];
    const float* Wp = (const float*)d_in[4];
    const float* bp = (const float*)d_in[5];
    float* out = (float*)d_out;

    cudaFuncSetAttribute(qkv_gemm_mma, cudaFuncAttributeMaxDynamicSharedMemorySize,
                         GEMM_SMEM_BYTES);
    cudaFuncSetAttribute(out_gemm_mma, cudaFuncAttributeMaxDynamicSharedMemorySize,
                         GEMM_SMEM_BYTES);
    cudaFuncSetAttribute(flash_mma, cudaFuncAttributeMaxDynamicSharedMemorySize,
                         FA_SMEM_U32 * 4);

    // 0) one-time conversions: x -> tf32, weights -> K-major tf32
    convert_x<<<BT_ * C_ / 1024, 256>>>(x);
    transpose_w<<<dim3(C_ / 32, HS_ / 32, 3 * H_), dim3(32, 8)>>>(Wq, Wk, Wv);
    transpose_wp<<<dim3(C_ / 32, C_ / 32), dim3(32, 8)>>>(Wp);
    // 1) QKV projection (tensor, tf32, cp.async 4-stage): M=4096, N=3072
    qkv_gemm_mma<<<dim3(3072 / 128, BT_ / 128), 256, GEMM_SMEM_BYTES>>>();
    // 2) Causal flash attention (R7 64-row, register P)
    flash_mma<<<dim3(T_ / 64, B_ * H_), 128, FA_SMEM_U32 * 4>>>();
    // 3) Output projection + bias (tensor, tf32, cp.async 4-stage)
    out_gemm_mma<<<dim3(C_ / 128, BT_ / 128), 256, GEMM_SMEM_BYTES>>>(bp, out);
}

// round 11
// speedup vs baseline: 1.0763x; 1.0107x over previous
#include <cuda_runtime.h>
#include <cstdint>

#define H_  16
#define HS_ 64
#define C_  1024
#define T_  2048
#define B_  2
#define BT_ (B_ * T_)   // 4096
#define LOG2E 1.4426950408889634f

// ---------------------------------------------------------------------------
// Scratch (no device allocation allowed)
// ---------------------------------------------------------------------------
__device__ float    g_q[B_ * H_ * T_ * HS_];
__device__ float    g_k[B_ * H_ * T_ * HS_];
__device__ float    g_v[B_ * H_ * T_ * HS_];
__device__ uint32_t g_att[BT_ * C_];            // tf32 bits (flash epilogue)
__device__ uint32_t g_xt[BT_ * C_];             // tf32 bits of x
__device__ uint32_t g_bt[3 * H_ * HS_ * C_];    // tf32 K-major QKV weights
__device__ uint32_t g_wpt[C_ * C_];             // tf32 K-major Wp

// ---------------------------------------------------------------------------
__device__ __forceinline__ uint32_t f2tf32(float f) {
    uint32_t r;
    asm("cvt.rna.tf32.f32 %0, %1;" : "=r"(r) : "f"(f));
    return r;
}
__device__ __forceinline__ float ex2f(float x) {
    float y;
    asm("ex2.approx.f32 %0, %1;" : "=f"(y) : "f"(x));
    return y;
}
__device__ __forceinline__ void mma_tf32(float c[4], const uint32_t a[4],
                                         const uint32_t b[2]) {
    asm volatile(
        "mma.sync.aligned.m16n8k8.row.col.f32.tf32.tf32.f32 "
        "{%0,%1,%2,%3}, {%4,%5,%6,%7}, {%8,%9}, {%0,%1,%2,%3};"
        : "+f"(c[0]), "+f"(c[1]), "+f"(c[2]), "+f"(c[3])
        : "r"(a[0]), "r"(a[1]), "r"(a[2]), "r"(a[3]), "r"(b[0]), "r"(b[1]));
}
__device__ __forceinline__ void cp_async16(void* dst, const void* src) {
    uint32_t d = (uint32_t)__cvta_generic_to_shared(dst);
    asm volatile("cp.async.cg.shared.global [%0], [%1], 16;"
                 :: "r"(d), "l"(src) : "memory");
}

// ---------------------------------------------------------------------------
// One-time input conversion: x -> tf32 bits
// ---------------------------------------------------------------------------
__global__ void convert_x(const float* __restrict__ x)
{
    const int i = (blockIdx.x * 256 + threadIdx.x) * 4;
    float4 v = *(const float4*)(x + i);
    uint4 t = {f2tf32(v.x), f2tf32(v.y), f2tf32(v.z), f2tf32(v.w)};
    *(uint4*)(g_xt + i) = t;
}

// ---------------------------------------------------------------------------
// Weight transposes into K-major tf32 scratch
// ---------------------------------------------------------------------------
__global__ void transpose_w(const float* __restrict__ Wq,
                            const float* __restrict__ Wk,
                            const float* __restrict__ Wv)
{
    __shared__ float tile[32][33];
    const int which = blockIdx.z >> 4;         // 0..2
    const int h     = blockIdx.z & 15;
    const float* W  = (which == 0) ? Wq : (which == 1) ? Wk : Wv;
    const int c0 = blockIdx.x * 32;
    const int d0 = blockIdx.y * 32;
    const int tx = threadIdx.x, ty = threadIdx.y;
#pragma unroll
    for (int j = 0; j < 32; j += 8)
        tile[ty + j][tx] = W[h * (C_ * HS_) + (c0 + ty + j) * HS_ + d0 + tx];
    __syncthreads();
    uint32_t* out = g_bt + (size_t)(which * 1024 + h * HS_ + d0) * C_ + c0;
#pragma unroll
    for (int j = 0; j < 32; j += 8)
        out[(ty + j) * C_ + tx] = f2tf32(tile[tx][ty + j]);
}

__global__ void transpose_wp(const float* __restrict__ Wp)
{
    __shared__ float tile[32][33];
    const int k0 = blockIdx.x * 32;
    const int n0 = blockIdx.y * 32;
    const int tx = threadIdx.x, ty = threadIdx.y;
#pragma unroll
    for (int j = 0; j < 32; j += 8)
        tile[ty + j][tx] = Wp[(k0 + ty + j) * C_ + n0 + tx];
    __syncthreads();
#pragma unroll
    for (int j = 0; j < 32; j += 8)
        g_wpt[(size_t)(n0 + ty + j) * C_ + k0 + tx] = f2tf32(tile[tx][ty + j]);
}

// ---------------------------------------------------------------------------
// tf32 mma.sync GEMM mainloop: 128x128 tile, K in 32-chunks, 4-stage cp.async
// pipeline + SOFTWARE-PIPELINED FRAGMENTS: the LDS for sub-iteration ks+1 is
// issued before the MMAs of ks, so LDS latency overlaps the tensor pipe.
// ---------------------------------------------------------------------------
#define NSTAGE   4
#define STG_U32  (2 * 128 * 36)
#define GEMM_SMEM_BYTES (NSTAGE * STG_U32 * 4)   // 147456

__device__ __forceinline__ void gemm_issue(uint32_t* gsm, int s,
                                           const uint32_t* Ap,
                                           const uint32_t* Bp,
                                           int k0, int lrow, int lc4)
{
    uint32_t* As = gsm + s * STG_U32;
    uint32_t* Bs = As + 128 * 36;
#pragma unroll
    for (int p = 0; p < 4; p++) {
        cp_async16(&As[(lrow + p * 32) * 36 + lc4], Ap + k0 + (size_t)p * 32 * C_);
        cp_async16(&Bs[(lrow + p * 32) * 36 + lc4], Bp + k0 + (size_t)p * 32 * C_);
    }
    asm volatile("cp.async.commit_group;" ::: "memory");
}

__device__ __forceinline__ void gemm_ldfrag(
    const uint32_t* As, const uint32_t* Bs, int k,
    int wm, int wn, int g, int t4,
    uint32_t af[4][4], uint32_t bf[4][2])
{
#pragma unroll
    for (int mt = 0; mt < 4; mt++) {
        const int r = wm + mt * 16 + g;
        af[mt][0] = As[r * 36 + k + t4];
        af[mt][1] = As[(r + 8) * 36 + k + t4];
        af[mt][2] = As[r * 36 + k + t4 + 4];
        af[mt][3] = As[(r + 8) * 36 + k + t4 + 4];
    }
#pragma unroll
    for (int nt = 0; nt < 4; nt++) {
        const int n = wn + nt * 8 + g;
        bf[nt][0] = Bs[n * 36 + k + t4];
        bf[nt][1] = Bs[n * 36 + k + t4 + 4];
    }
}

__device__ __forceinline__ void gemm_core(
    const uint32_t* __restrict__ A, const uint32_t* __restrict__ Bt,
    int m0, int n0, float acc[4][4][4], uint32_t* gsm)
{
    const int tid  = threadIdx.x;
    const int wid  = tid >> 5;
    const int lane = tid & 31;
    const int wm = (wid & 1) * 64;
    const int wn = (wid >> 1) * 32;
    const int g  = lane >> 2;
    const int t4 = lane & 3;

    const int lrow = tid >> 3;        // 0..31, + p*32
    const int lc4  = (tid & 7) * 4;   // k-col (u32)

    const uint32_t* Ap = A + (size_t)(m0 + lrow) * C_ + lc4;
    const uint32_t* Bp = Bt + (size_t)(n0 + lrow) * C_ + lc4;

#pragma unroll
    for (int mt = 0; mt < 4; mt++)
#pragma unroll
        for (int nt = 0; nt < 4; nt++)
#pragma unroll
            for (int i = 0; i < 4; i++) acc[mt][nt][i] = 0.f;

    gemm_issue(gsm, 0, Ap, Bp, 0,  lrow, lc4);
    gemm_issue(gsm, 1, Ap, Bp, 32, lrow, lc4);
    gemm_issue(gsm, 2, Ap, Bp, 64, lrow, lc4);

    uint32_t af[2][4][4], bf[2][4][2];

#pragma unroll 1
    for (int it = 0; it < 32; ++it) {
        if (it < 30)       asm volatile("cp.async.wait_group 2;" ::: "memory");
        else if (it == 30) asm volatile("cp.async.wait_group 1;" ::: "memory");
        else               asm volatile("cp.async.wait_group 0;" ::: "memory");
        __syncthreads();   // chunk `it` visible; buffer (it+3)%4 free

        if (it + 3 < 32)
            gemm_issue(gsm, (it + 3) & 3, Ap, Bp, (it + 3) * 32, lrow, lc4);

        const uint32_t* As = gsm + (it & 3) * STG_U32;
        const uint32_t* Bs = As + 128 * 36;

        gemm_ldfrag(As, Bs, 0, wm, wn, g, t4, af[0], bf[0]);
#pragma unroll
        for (int ks = 0; ks < 4; ks++) {
            const int cur = ks & 1;
            if (ks < 3)
                gemm_ldfrag(As, Bs, (ks + 1) * 8, wm, wn, g, t4,
                            af[cur ^ 1], bf[cur ^ 1]);
#pragma unroll
            for (int mt = 0; mt < 4; mt++)
#pragma unroll
                for (int nt = 0; nt < 4; nt++)
                    mma_tf32(acc[mt][nt], af[cur][mt], bf[cur][nt]);
        }
    }
}

// ---------------------------------------------------------------------------
// QKV projection: M=4096 (b,t), N=3072 (qkv,h,d), K=1024
// ---------------------------------------------------------------------------
__global__ __launch_bounds__(256) void qkv_gemm_mma()
{
    extern __shared__ uint32_t gsm[];
    const int m0 = blockIdx.y * 128;
    const int n0 = blockIdx.x * 128;

    float acc[4][4][4];
    gemm_core(g_xt, g_bt, m0, n0, acc, gsm);

    const int tid  = threadIdx.x;
    const int wid  = tid >> 5;
    const int lane = tid & 31;
    const int wm = (wid & 1) * 64;
    const int wn = (wid >> 1) * 32;
    const int g  = lane >> 2;
    const int t4 = lane & 3;

#pragma unroll
    for (int mt = 0; mt < 4; mt++) {
#pragma unroll
        for (int nt = 0; nt < 4; nt++) {
            const int n  = n0 + wn + nt * 8 + t4 * 2;
            const int qk = n >> 10;
            const int h2 = (n >> 6) & (H_ - 1);
            const int d2 = n & (HS_ - 1);
            float* base = ((qk == 0) ? g_q : (qk == 1) ? g_k : g_v);
#pragma unroll
            for (int half = 0; half < 2; half++) {
                const int m = m0 + wm + mt * 16 + g + half * 8;
                const int b = m >> 11;
                const int t = m & (T_ - 1);
                float2 v;
                v.x = acc[mt][nt][half * 2 + 0];
                v.y = acc[mt][nt][half * 2 + 1];
                *(float2*)&base[(((size_t)b * H_ + h2) * T_ + t) * HS_ + d2] = v;
            }
        }
    }
}

// ---------------------------------------------------------------------------
// Output projection: M=4096, N=1024, K=1024, + bias
// ---------------------------------------------------------------------------
__global__ __launch_bounds__(256) void out_gemm_mma(const float* __restrict__ bp,
                                                    float* __restrict__ out)
{
    extern __shared__ uint32_t gsm[];
    const int m0 = blockIdx.y * 128;
    const int n0 = blockIdx.x * 128;

    float acc[4][4][4];
    gemm_core(g_att, g_wpt, m0, n0, acc, gsm);

    const int tid  = threadIdx.x;
    const int wid  = tid >> 5;
    const int lane = tid & 31;
    const int wm = (wid & 1) * 64;
    const int wn = (wid >> 1) * 32;
    const int g  = lane >> 2;
    const int t4 = lane & 3;

#pragma unroll
    for (int mt = 0; mt < 4; mt++) {
#pragma unroll
        for (int nt = 0; nt < 4; nt++) {
            const int n = n0 + wn + nt * 8 + t4 * 2;
            const float2 bias = *(const float2*)(bp + n);
#pragma unroll
            for (int half = 0; half < 2; half++) {
                const int m = m0 + wm + mt * 16 + g + half * 8;
                float2 v;
                v.x = acc[mt][nt][half * 2 + 0] + bias.x;
                v.y = acc[mt][nt][half * 2 + 1] + bias.y;
                *(float2*)&out[(size_t)m * C_ + n] = v;
            }
        }
    }
}

// ---------------------------------------------------------------------------
// Flash attention (R7-proven 64-row version), tf32 mma.sync, register P.
// Epilogue writes g_att as tf32 bits (pre-converted for the output GEMM).
// ---------------------------------------------------------------------------
#define FA_SMEM_U32 (64 * 68 + 64 * 72)

__global__ __launch_bounds__(128, 3) void flash_mma()
{
    extern __shared__ uint32_t sm[];
    uint32_t* Ks = sm;                    // [64][68]
    uint32_t* Vs = sm + 64 * 68;          // [64][72]

    const int qt  = gridDim.x - 1 - blockIdx.x;   // long blocks first
    const int bh  = blockIdx.y;
    const int tid = threadIdx.x;
    const int wid = tid >> 5, lane = tid & 31;
    const int g = lane >> 2, t4 = lane & 3;
    const int wr = wid * 16;
    const int q0 = qt * 64;

    const float* qb = g_q + (size_t)bh * T_ * HS_;
    const float* kb = g_k + (size_t)bh * T_ * HS_;
    const float* vb = g_v + (size_t)bh * T_ * HS_;

    // stage Q through Ks (scale folded: 1/sqrt(HS) * log2(e)), tf32
    const float qscale = 0.125f * LOG2E;
#pragma unroll
    for (int it = 0; it < 8; it++) {
        int l = it * 128 + tid, r = l >> 4, c4 = (l & 15) * 4;
        float4 v = *(const float4*)(qb + (size_t)(q0 + r) * HS_ + c4);
        uint32_t* d = &Ks[r * 68 + c4];
        d[0] = f2tf32(v.x * qscale); d[1] = f2tf32(v.y * qscale);
        d[2] = f2tf32(v.z * qscale); d[3] = f2tf32(v.w * qscale);
    }
    __syncthreads();

    uint32_t qa[8][4];
#pragma unroll
    for (int kk = 0; kk < 8; kk++) {
        qa[kk][0] = Ks[(wr + g) * 68 + t4 + 8 * kk];
        qa[kk][1] = Ks[(wr + g + 8) * 68 + t4 + 8 * kk];
        qa[kk][2] = Ks[(wr + g) * 68 + t4 + 4 + 8 * kk];
        qa[kk][3] = Ks[(wr + g + 8) * 68 + t4 + 4 + 8 * kk];
    }

    float oacc[8][4];
#pragma unroll
    for (int nt = 0; nt < 8; nt++)
#pragma unroll
        for (int i = 0; i < 4; i++) oacc[nt][i] = 0.f;
    float m0 = -1e30f, m1 = -1e30f, l0 = 0.f, l1 = 0.f;

    // P shuffle mapping: P[g][t4+8kk] lives in lane g*4+(t4>>1), comp t4&1
    const int src0 = g * 4 + (t4 >> 1);
    const int src2 = src0 + 2;
    const bool sel = (t4 & 1) != 0;

#pragma unroll 1
    for (int kt = 0; kt <= qt; kt++) {
        const int k0 = kt * 64;
        __syncthreads();   // prior tile's Ks/Vs consumers (and qa reads) done
#pragma unroll
        for (int it = 0; it < 8; it++) {
            int l = it * 128 + tid, r = l >> 4, c4 = (l & 15) * 4;
            float4 kv = *(const float4*)(kb + (size_t)(k0 + r) * HS_ + c4);
            uint32_t* dk = &Ks[r * 68 + c4];
            dk[0] = f2tf32(kv.x); dk[1] = f2tf32(kv.y);
            dk[2] = f2tf32(kv.z); dk[3] = f2tf32(kv.w);
            float4 vv = *(const float4*)(vb + (size_t)(k0 + r) * HS_ + c4);
            uint32_t* dv = &Vs[r * 72 + c4];
            dv[0] = f2tf32(vv.x); dv[1] = f2tf32(vv.y);
            dv[2] = f2tf32(vv.z); dv[3] = f2tf32(vv.w);
        }
        __syncthreads();

        // S = Q K^T  (units: log2)
        float sacc[8][4];
#pragma unroll
        for (int nt = 0; nt < 8; nt++)
#pragma unroll
            for (int i = 0; i < 4; i++) sacc[nt][i] = 0.f;
#pragma unroll
        for (int kk = 0; kk < 8; kk++) {
#pragma unroll
            for (int nt = 0; nt < 8; nt++) {
                uint32_t bf[2];
                bf[0] = Ks[(g + 8 * nt) * 68 + t4 + 8 * kk];
                bf[1] = Ks[(g + 8 * nt) * 68 + t4 + 4 + 8 * kk];
                mma_tf32(sacc[nt], qa[kk], bf);
            }
        }

        if (kt == qt) {   // causal mask on the diagonal tile (local coords)
            const int r0 = wr + g, r1 = wr + g + 8;
#pragma unroll
            for (int nt = 0; nt < 8; nt++) {
                const int c = 8 * nt + 2 * t4;
                if (c     > r0) sacc[nt][0] = -1e30f;
                if (c + 1 > r0) sacc[nt][1] = -1e30f;
                if (c     > r1) sacc[nt][2] = -1e30f;
                if (c + 1 > r1) sacc[nt][3] = -1e30f;
            }
        }

        // online softmax (base 2)
        float ml0 = -1e30f, ml1 = -1e30f;
#pragma unroll
        for (int nt = 0; nt < 8; nt++) {
            ml0 = fmaxf(ml0, fmaxf(sacc[nt][0], sacc[nt][1]));
            ml1 = fmaxf(ml1, fmaxf(sacc[nt][2], sacc[nt][3]));
        }
        ml0 = fmaxf(ml0, __shfl_xor_sync(0xffffffffu, ml0, 1));
        ml0 = fmaxf(ml0, __shfl_xor_sync(0xffffffffu, ml0, 2));
        ml1 = fmaxf(ml1, __shfl_xor_sync(0xffffffffu, ml1, 1));
        ml1 = fmaxf(ml1, __shfl_xor_sync(0xffffffffu, ml1, 2));
        const float mn0 = fmaxf(m0, ml0), mn1 = fmaxf(m1, ml1);
        const float corr0 = ex2f(m0 - mn0), corr1 = ex2f(m1 - mn1);
        m0 = mn0; m1 = mn1;

        uint32_t pu[8][4];
        float ps0 = 0.f, ps1 = 0.f;
#pragma unroll
        for (int nt = 0; nt < 8; nt++) {
            float p00 = ex2f(sacc[nt][0] - mn0);
            float p01 = ex2f(sacc[nt][1] - mn0);
            float p10 = ex2f(sacc[nt][2] - mn1);
            float p11 = ex2f(sacc[nt][3] - mn1);
            ps0 += p00 + p01;
            ps1 += p10 + p11;
            pu[nt][0] = f2tf32(p00); pu[nt][1] = f2tf32(p01);
            pu[nt][2] = f2tf32(p10); pu[nt][3] = f2tf32(p11);
            oacc[nt][0] *= corr0; oacc[nt][1] *= corr0;
            oacc[nt][2] *= corr1; oacc[nt][3] *= corr1;
        }
        ps0 += __shfl_xor_sync(0xffffffffu, ps0, 1);
        ps0 += __shfl_xor_sync(0xffffffffu, ps0, 2);
        ps1 += __shfl_xor_sync(0xffffffffu, ps1, 1);
        ps1 += __shfl_xor_sync(0xffffffffu, ps1, 2);
        l0 = l0 * corr0 + ps0;
        l1 = l1 * corr1 + ps1;

        // O += P V  (P redistributed C-frag -> A-frag via shuffles)
#pragma unroll
        for (int kk = 0; kk < 8; kk++) {
            uint32_t pa[4];
            uint32_t v0 = __shfl_sync(0xffffffffu, pu[kk][0], src0);
            uint32_t v1 = __shfl_sync(0xffffffffu, pu[kk][1], src0);
            uint32_t v2 = __shfl_sync(0xffffffffu, pu[kk][2], src0);
            uint32_t v3 = __shfl_sync(0xffffffffu, pu[kk][3], src0);
            pa[0] = sel ? v1 : v0;    // P[g][t4+8kk]
            pa[1] = sel ? v3 : v2;    // P[g+8][t4+8kk]
            uint32_t w0 = __shfl_sync(0xffffffffu, pu[kk][0], src2);
            uint32_t w1 = __shfl_sync(0xffffffffu, pu[kk][1], src2);
            uint32_t w2 = __shfl_sync(0xffffffffu, pu[kk][2], src2);
            uint32_t w3 = __shfl_sync(0xffffffffu, pu[kk][3], src2);
            pa[2] = sel ? w1 : w0;    // P[g][t4+4+8kk]
            pa[3] = sel ? w3 : w2;    // P[g+8][t4+4+8kk]
#pragma unroll
            for (int nt = 0; nt < 8; nt++) {
                uint32_t bf[2];
                bf[0] = Vs[(t4 + 8 * kk) * 72 + g + 8 * nt];
                bf[1] = Vs[(t4 + 4 + 8 * kk) * 72 + g + 8 * nt];
                mma_tf32(oacc[nt], pa, bf);
            }
        }
    }

    // epilogue: normalize, convert to tf32 bits, write g_att[b, t, h*64 + hs]
    const float inv0 = 1.0f / l0, inv1 = 1.0f / l1;
    const int b = bh >> 4;
    const int h = bh & (H_ - 1);
    const int qrow0 = q0 + wr + g;
    const int qrow1 = qrow0 + 8;
    uint32_t* dst0 = g_att + ((size_t)b * T_ + qrow0) * C_ + h * HS_;
    uint32_t* dst1 = g_att + ((size_t)b * T_ + qrow1) * C_ + h * HS_;
#pragma unroll
    for (int nt = 0; nt < 8; nt++) {
        uint2 v0 = {f2tf32(oacc[nt][0] * inv0), f2tf32(oacc[nt][1] * inv0)};
        *(uint2*)&dst0[8 * nt + 2 * t4] = v0;
        uint2 v1 = {f2tf32(oacc[nt][2] * inv1), f2tf32(oacc[nt][3] * inv1)};
        *(uint2*)&dst1[8 * nt + 2 * t4] = v1;
    }
}

// ---------------------------------------------------------------------------
extern "C" void kernel_launch(void* const* d_in, const int* in_sizes, int n_in,
                              void* d_out, int out_size)
{
    const float* x  = (const float*)d_in[0];
    const float* Wq = (const float*)d_in[1];
    const float* Wk = (const float*)d_in[2];
    const float* Wv = (const float*)d_in[3];
    const float* Wp = (const float*)d_in[4];
    const float* bp = (const float*)d_in[5];
    float* out = (float*)d_out;

    cudaFuncSetAttribute(qkv_gemm_mma, cudaFuncAttributeMaxDynamicSharedMemorySize,
                         GEMM_SMEM_BYTES);
    cudaFuncSetAttribute(out_gemm_mma, cudaFuncAttributeMaxDynamicSharedMemorySize,
                         GEMM_SMEM_BYTES);
    cudaFuncSetAttribute(flash_mma, cudaFuncAttributeMaxDynamicSharedMemorySize,
                         FA_SMEM_U32 * 4);

    // 0) one-time conversions: x -> tf32, weights -> K-major tf32
    convert_x<<<BT_ * C_ / 1024, 256>>>(x);
    transpose_w<<<dim3(C_ / 32, HS_ / 32, 3 * H_), dim3(32, 8)>>>(Wq, Wk, Wv);
    transpose_wp<<<dim3(C_ / 32, C_ / 32), dim3(32, 8)>>>(Wp);
    // 1) QKV projection (tensor, tf32, cp.async + frag pipeline)
    qkv_gemm_mma<<<dim3(3072 / 128, BT_ / 128), 256, GEMM_SMEM_BYTES>>>();
    // 2) Causal flash attention (R7 64-row, register P)
    flash_mma<<<dim3(T_ / 64, B_ * H_), 128, FA_SMEM_U32 * 4>>>();
    // 3) Output projection + bias (tensor, tf32, cp.async + frag pipeline)
    out_gemm_mma<<<dim3(C_ / 128, BT_ / 128), 256, GEMM_SMEM_BYTES>>>(bp, out);
}

// round 13
// speedup vs baseline: 1.1446x; 1.0635x over previous
#include <cuda_runtime.h>
#include <cstdint>

#define H_  16
#define HS_ 64
#define C_  1024
#define T_  2048
#define B_  2
#define BT_ (B_ * T_)   // 4096
#define LOG2E 1.4426950408889634f

// ---------------------------------------------------------------------------
// Scratch (no device allocation allowed)
// ---------------------------------------------------------------------------
__device__ float    g_q[B_ * H_ * T_ * HS_];
__device__ float    g_k[B_ * H_ * T_ * HS_];
__device__ float    g_v[B_ * H_ * T_ * HS_];
__device__ uint32_t g_att[BT_ * C_];            // tf32 bits (flash epilogue)
__device__ uint32_t g_xt[BT_ * C_];             // tf32 bits of x
__device__ uint32_t g_bt[3 * H_ * HS_ * C_];    // tf32 K-major QKV weights
__device__ uint32_t g_wpt[C_ * C_];             // tf32 K-major Wp

// ---------------------------------------------------------------------------
__device__ __forceinline__ uint32_t f2tf32(float f) {
    uint32_t r;
    asm("cvt.rna.tf32.f32 %0, %1;" : "=r"(r) : "f"(f));
    return r;
}
__device__ __forceinline__ float ex2f(float x) {
    float y;
    asm("ex2.approx.f32 %0, %1;" : "=f"(y) : "f"(x));
    return y;
}
__device__ __forceinline__ void mma_tf32(float c[4], const uint32_t a[4],
                                         const uint32_t b[2]) {
    asm volatile(
        "mma.sync.aligned.m16n8k8.row.col.f32.tf32.tf32.f32 "
        "{%0,%1,%2,%3}, {%4,%5,%6,%7}, {%8,%9}, {%0,%1,%2,%3};"
        : "+f"(c[0]), "+f"(c[1]), "+f"(c[2]), "+f"(c[3])
        : "r"(a[0]), "r"(a[1]), "r"(a[2]), "r"(a[3]), "r"(b[0]), "r"(b[1]));
}
__device__ __forceinline__ void cp_async16(void* dst, const void* src) {
    uint32_t d = (uint32_t)__cvta_generic_to_shared(dst);
    asm volatile("cp.async.cg.shared.global [%0], [%1], 16;"
                 :: "r"(d), "l"(src) : "memory");
}

// ---------------------------------------------------------------------------
// One-time input conversion: x -> tf32 bits
// ---------------------------------------------------------------------------
__global__ void convert_x(const float* __restrict__ x)
{
    const int i = (blockIdx.x * 256 + threadIdx.x) * 4;
    float4 v = *(const float4*)(x + i);
    uint4 t = {f2tf32(v.x), f2tf32(v.y), f2tf32(v.z), f2tf32(v.w)};
    *(uint4*)(g_xt + i) = t;
}

// ---------------------------------------------------------------------------
// Weight transposes into K-major tf32 scratch
// ---------------------------------------------------------------------------
__global__ void transpose_w(const float* __restrict__ Wq,
                            const float* __restrict__ Wk,
                            const float* __restrict__ Wv)
{
    __shared__ float tile[32][33];
    const int which = blockIdx.z >> 4;         // 0..2
    const int h     = blockIdx.z & 15;
    const float* W  = (which == 0) ? Wq : (which == 1) ? Wk : Wv;
    const int c0 = blockIdx.x * 32;
    const int d0 = blockIdx.y * 32;
    const int tx = threadIdx.x, ty = threadIdx.y;
#pragma unroll
    for (int j = 0; j < 32; j += 8)
        tile[ty + j][tx] = W[h * (C_ * HS_) + (c0 + ty + j) * HS_ + d0 + tx];
    __syncthreads();
    uint32_t* out = g_bt + (size_t)(which * 1024 + h * HS_ + d0) * C_ + c0;
#pragma unroll
    for (int j = 0; j < 32; j += 8)
        out[(ty + j) * C_ + tx] = f2tf32(tile[tx][ty + j]);
}

__global__ void transpose_wp(const float* __restrict__ Wp)
{
    __shared__ float tile[32][33];
    const int k0 = blockIdx.x * 32;
    const int n0 = blockIdx.y * 32;
    const int tx = threadIdx.x, ty = threadIdx.y;
#pragma unroll
    for (int j = 0; j < 32; j += 8)
        tile[ty + j][tx] = Wp[(k0 + ty + j) * C_ + n0 + tx];
    __syncthreads();
#pragma unroll
    for (int j = 0; j < 32; j += 8)
        g_wpt[(size_t)(n0 + ty + j) * C_ + k0 + tx] = f2tf32(tile[tx][ty + j]);
}

// ---------------------------------------------------------------------------
// tf32 mma.sync GEMM mainloop: 128x128 tile, K in 32-chunks, 3-stage cp.async
// pipeline sized so TWO CTAs fit per SM (110.6 KB each) -> 4 warps/SMSP to
// cover the LDS->MMA dependency latency that capped issue at 22% with 1 CTA.
// ---------------------------------------------------------------------------
#define NSTAGE   3
#define STG_U32  (2 * 128 * 36)
#define GEMM_SMEM_BYTES (NSTAGE * STG_U32 * 4)   // 110592

__device__ __forceinline__ void gemm_issue(uint32_t* gsm, int s,
                                           const uint32_t* Ap,
                                           const uint32_t* Bp,
                                           int k0, int lrow, int lc4)
{
    uint32_t* As = gsm + s * STG_U32;
    uint32_t* Bs = As + 128 * 36;
#pragma unroll
    for (int p = 0; p < 4; p++) {
        cp_async16(&As[(lrow + p * 32) * 36 + lc4], Ap + k0 + (size_t)p * 32 * C_);
        cp_async16(&Bs[(lrow + p * 32) * 36 + lc4], Bp + k0 + (size_t)p * 32 * C_);
    }
    asm volatile("cp.async.commit_group;" ::: "memory");
}

__device__ __forceinline__ void gemm_core(
    const uint32_t* __restrict__ A, const uint32_t* __restrict__ Bt,
    int m0, int n0, float acc[4][4][4], uint32_t* gsm)
{
    const int tid  = threadIdx.x;
    const int wid  = tid >> 5;
    const int lane = tid & 31;
    const int wm = (wid & 1) * 64;
    const int wn = (wid >> 1) * 32;
    const int g  = lane >> 2;
    const int t4 = lane & 3;

    const int lrow = tid >> 3;        // 0..31, + p*32
    const int lc4  = (tid & 7) * 4;   // k-col (u32)

    const uint32_t* Ap = A + (size_t)(m0 + lrow) * C_ + lc4;
    const uint32_t* Bp = Bt + (size_t)(n0 + lrow) * C_ + lc4;

#pragma unroll
    for (int mt = 0; mt < 4; mt++)
#pragma unroll
        for (int nt = 0; nt < 4; nt++)
#pragma unroll
            for (int i = 0; i < 4; i++) acc[mt][nt][i] = 0.f;

    gemm_issue(gsm, 0, Ap, Bp, 0,  lrow, lc4);
    gemm_issue(gsm, 1, Ap, Bp, 32, lrow, lc4);

#pragma unroll 1
    for (int it = 0; it < 32; ++it) {
        if (it < 31) asm volatile("cp.async.wait_group 1;" ::: "memory");
        else         asm volatile("cp.async.wait_group 0;" ::: "memory");
        __syncthreads();   // chunk `it` visible; buffer (it+2)%3 free

        if (it + 2 < 32)
            gemm_issue(gsm, (it + 2) % 3, Ap, Bp, (it + 2) * 32, lrow, lc4);

        const uint32_t* As = gsm + (it % 3) * STG_U32;
        const uint32_t* Bs = As + 128 * 36;
#pragma unroll
        for (int ks = 0; ks < 4; ks++) {
            const int k = ks * 8;
            uint32_t af[4][4], bf[4][2];
#pragma unroll
            for (int mt = 0; mt < 4; mt++) {
                const int r = wm + mt * 16 + g;
                af[mt][0] = As[r * 36 + k + t4];
                af[mt][1] = As[(r + 8) * 36 + k + t4];
                af[mt][2] = As[r * 36 + k + t4 + 4];
                af[mt][3] = As[(r + 8) * 36 + k + t4 + 4];
            }
#pragma unroll
            for (int nt = 0; nt < 4; nt++) {
                const int n = wn + nt * 8 + g;
                bf[nt][0] = Bs[n * 36 + k + t4];
                bf[nt][1] = Bs[n * 36 + k + t4 + 4];
            }
#pragma unroll
            for (int mt = 0; mt < 4; mt++)
#pragma unroll
                for (int nt = 0; nt < 4; nt++)
                    mma_tf32(acc[mt][nt], af[mt], bf[nt]);
        }
    }
}

// ---------------------------------------------------------------------------
// QKV projection: M=4096 (b,t), N=3072 (qkv,h,d), K=1024
// ---------------------------------------------------------------------------
__global__ __launch_bounds__(256, 2) void qkv_gemm_mma()
{
    extern __shared__ uint32_t gsm[];
    const int m0 = blockIdx.y * 128;
    const int n0 = blockIdx.x * 128;

    float acc[4][4][4];
    gemm_core(g_xt, g_bt, m0, n0, acc, gsm);

    const int tid  = threadIdx.x;
    const int wid  = tid >> 5;
    const int lane = tid & 31;
    const int wm = (wid & 1) * 64;
    const int wn = (wid >> 1) * 32;
    const int g  = lane >> 2;
    const int t4 = lane & 3;

#pragma unroll
    for (int mt = 0; mt < 4; mt++) {
#pragma unroll
        for (int nt = 0; nt < 4; nt++) {
            const int n  = n0 + wn + nt * 8 + t4 * 2;
            const int qk = n >> 10;
            const int h2 = (n >> 6) & (H_ - 1);
            const int d2 = n & (HS_ - 1);
            float* base = ((qk == 0) ? g_q : (qk == 1) ? g_k : g_v);
#pragma unroll
            for (int half = 0; half < 2; half++) {
                const int m = m0 + wm + mt * 16 + g + half * 8;
                const int b = m >> 11;
                const int t = m & (T_ - 1);
                float2 v;
                v.x = acc[mt][nt][half * 2 + 0];
                v.y = acc[mt][nt][half * 2 + 1];
                *(float2*)&base[(((size_t)b * H_ + h2) * T_ + t) * HS_ + d2] = v;
            }
        }
    }
}

// ---------------------------------------------------------------------------
// Output projection: M=4096, N=1024, K=1024, + bias
// ---------------------------------------------------------------------------
__global__ __launch_bounds__(256, 2) void out_gemm_mma(const float* __restrict__ bp,
                                                       float* __restrict__ out)
{
    extern __shared__ uint32_t gsm[];
    const int m0 = blockIdx.y * 128;
    const int n0 = blockIdx.x * 128;

    float acc[4][4][4];
    gemm_core(g_att, g_wpt, m0, n0, acc, gsm);

    const int tid  = threadIdx.x;
    const int wid  = tid >> 5;
    const int lane = tid & 31;
    const int wm = (wid & 1) * 64;
    const int wn = (wid >> 1) * 32;
    const int g  = lane >> 2;
    const int t4 = lane & 3;

#pragma unroll
    for (int mt = 0; mt < 4; mt++) {
#pragma unroll
        for (int nt = 0; nt < 4; nt++) {
            const int n = n0 + wn + nt * 8 + t4 * 2;
            const float2 bias = *(const float2*)(bp + n);
#pragma unroll
            for (int half = 0; half < 2; half++) {
                const int m = m0 + wm + mt * 16 + g + half * 8;
                float2 v;
                v.x = acc[mt][nt][half * 2 + 0] + bias.x;
                v.y = acc[mt][nt][half * 2 + 1] + bias.y;
                *(float2*)&out[(size_t)m * C_ + n] = v;
            }
        }
    }
}

// ---------------------------------------------------------------------------
// Flash attention (R7-proven 64-row version), tf32 mma.sync, register P.
// Epilogue writes g_att as tf32 bits (pre-converted for the output GEMM).
// ---------------------------------------------------------------------------
#define FA_SMEM_U32 (64 * 68 + 64 * 72)

__global__ __launch_bounds__(128, 3) void flash_mma()
{
    extern __shared__ uint32_t sm[];
    uint32_t* Ks = sm;                    // [64][68]
    uint32_t* Vs = sm + 64 * 68;          // [64][72]

    const int qt  = gridDim.x - 1 - blockIdx.x;   // long blocks first
    const int bh  = blockIdx.y;
    const int tid = threadIdx.x;
    const int wid = tid >> 5, lane = tid & 31;
    const int g = lane >> 2, t4 = lane & 3;
    const int wr = wid * 16;
    const int q0 = qt * 64;

    const float* qb = g_q + (size_t)bh * T_ * HS_;
    const float* kb = g_k + (size_t)bh * T_ * HS_;
    const float* vb = g_v + (size_t)bh * T_ * HS_;

    // stage Q through Ks (scale folded: 1/sqrt(HS) * log2(e)), tf32
    const float qscale = 0.125f * LOG2E;
#pragma unroll
    for (int it = 0; it < 8; it++) {
        int l = it * 128 + tid, r = l >> 4, c4 = (l & 15) * 4;
        float4 v = *(const float4*)(qb + (size_t)(q0 + r) * HS_ + c4);
        uint32_t* d = &Ks[r * 68 + c4];
        d[0] = f2tf32(v.x * qscale); d[1] = f2tf32(v.y * qscale);
        d[2] = f2tf32(v.z * qscale); d[3] = f2tf32(v.w * qscale);
    }
    __syncthreads();

    uint32_t qa[8][4];
#pragma unroll
    for (int kk = 0; kk < 8; kk++) {
        qa[kk][0] = Ks[(wr + g) * 68 + t4 + 8 * kk];
        qa[kk][1] = Ks[(wr + g + 8) * 68 + t4 + 8 * kk];
        qa[kk][2] = Ks[(wr + g) * 68 + t4 + 4 + 8 * kk];
        qa[kk][3] = Ks[(wr + g + 8) * 68 + t4 + 4 + 8 * kk];
    }

    float oacc[8][4];
#pragma unroll
    for (int nt = 0; nt < 8; nt++)
#pragma unroll
        for (int i = 0; i < 4; i++) oacc[nt][i] = 0.f;
    float m0 = -1e30f, m1 = -1e30f, l0 = 0.f, l1 = 0.f;

    // P shuffle mapping: P[g][t4+8kk] lives in lane g*4+(t4>>1), comp t4&1
    const int src0 = g * 4 + (t4 >> 1);
    const int src2 = src0 + 2;
    const bool sel = (t4 & 1) != 0;

#pragma unroll 1
    for (int kt = 0; kt <= qt; kt++) {
        const int k0 = kt * 64;
        __syncthreads();   // prior tile's Ks/Vs consumers (and qa reads) done
#pragma unroll
        for (int it = 0; it < 8; it++) {
            int l = it * 128 + tid, r = l >> 4, c4 = (l & 15) * 4;
            float4 kv = *(const float4*)(kb + (size_t)(k0 + r) * HS_ + c4);
            uint32_t* dk = &Ks[r * 68 + c4];
            dk[0] = f2tf32(kv.x); dk[1] = f2tf32(kv.y);
            dk[2] = f2tf32(kv.z); dk[3] = f2tf32(kv.w);
            float4 vv = *(const float4*)(vb + (size_t)(k0 + r) * HS_ + c4);
            uint32_t* dv = &Vs[r * 72 + c4];
            dv[0] = f2tf32(vv.x); dv[1] = f2tf32(vv.y);
            dv[2] = f2tf32(vv.z); dv[3] = f2tf32(vv.w);
        }
        __syncthreads();

        // S = Q K^T  (units: log2)
        float sacc[8][4];
#pragma unroll
        for (int nt = 0; nt < 8; nt++)
#pragma unroll
            for (int i = 0; i < 4; i++) sacc[nt][i] = 0.f;
#pragma unroll
        for (int kk = 0; kk < 8; kk++) {
#pragma unroll
            for (int nt = 0; nt < 8; nt++) {
                uint32_t bf[2];
                bf[0] = Ks[(g + 8 * nt) * 68 + t4 + 8 * kk];
                bf[1] = Ks[(g + 8 * nt) * 68 + t4 + 4 + 8 * kk];
                mma_tf32(sacc[nt], qa[kk], bf);
            }
        }

        if (kt == qt) {   // causal mask on the diagonal tile (local coords)
            const int r0 = wr + g, r1 = wr + g + 8;
#pragma unroll
            for (int nt = 0; nt < 8; nt++) {
                const int c = 8 * nt + 2 * t4;
                if (c     > r0) sacc[nt][0] = -1e30f;
                if (c + 1 > r0) sacc[nt][1] = -1e30f;
                if (c     > r1) sacc[nt][2] = -1e30f;
                if (c + 1 > r1) sacc[nt][3] = -1e30f;
            }
        }

        // online softmax (base 2)
        float ml0 = -1e30f, ml1 = -1e30f;
#pragma unroll
        for (int nt = 0; nt < 8; nt++) {
            ml0 = fmaxf(ml0, fmaxf(sacc[nt][0], sacc[nt][1]));
            ml1 = fmaxf(ml1, fmaxf(sacc[nt][2], sacc[nt][3]));
        }
        ml0 = fmaxf(ml0, __shfl_xor_sync(0xffffffffu, ml0, 1));
        ml0 = fmaxf(ml0, __shfl_xor_sync(0xffffffffu, ml0, 2));
        ml1 = fmaxf(ml1, __shfl_xor_sync(0xffffffffu, ml1, 1));
        ml1 = fmaxf(ml1, __shfl_xor_sync(0xffffffffu, ml1, 2));
        const float mn0 = fmaxf(m0, ml0), mn1 = fmaxf(m1, ml1);
        const float corr0 = ex2f(m0 - mn0), corr1 = ex2f(m1 - mn1);
        m0 = mn0; m1 = mn1;

        uint32_t pu[8][4];
        float ps0 = 0.f, ps1 = 0.f;
#pragma unroll
        for (int nt = 0; nt < 8; nt++) {
            float p00 = ex2f(sacc[nt][0] - mn0);
            float p01 = ex2f(sacc[nt][1] - mn0);
            float p10 = ex2f(sacc[nt][2] - mn1);
            float p11 = ex2f(sacc[nt][3] - mn1);
            ps0 += p00 + p01;
            ps1 += p10 + p11;
            pu[nt][0] = f2tf32(p00); pu[nt][1] = f2tf32(p01);
            pu[nt][2] = f2tf32(p10); pu[nt][3] = f2tf32(p11);
            oacc[nt][0] *= corr0; oacc[nt][1] *= corr0;
            oacc[nt][2] *= corr1; oacc[nt][3] *= corr1;
        }
        ps0 += __shfl_xor_sync(0xffffffffu, ps0, 1);
        ps0 += __shfl_xor_sync(0xffffffffu, ps0, 2);
        ps1 += __shfl_xor_sync(0xffffffffu, ps1, 1);
        ps1 += __shfl_xor_sync(0xffffffffu, ps1, 2);
        l0 = l0 * corr0 + ps0;
        l1 = l1 * corr1 + ps1;

        // O += P V  (P redistributed C-frag -> A-frag via shuffles)
#pragma unroll
        for (int kk = 0; kk < 8; kk++) {
            uint32_t pa[4];
            uint32_t v0 = __shfl_sync(0xffffffffu, pu[kk][0], src0);
            uint32_t v1 = __shfl_sync(0xffffffffu, pu[kk][1], src0);
            uint32_t v2 = __shfl_sync(0xffffffffu, pu[kk][2], src0);
            uint32_t v3 = __shfl_sync(0xffffffffu, pu[kk][3], src0);
            pa[0] = sel ? v1 : v0;    // P[g][t4+8kk]
            pa[1] = sel ? v3 : v2;    // P[g+8][t4+8kk]
            uint32_t w0 = __shfl_sync(0xffffffffu, pu[kk][0], src2);
            uint32_t w1 = __shfl_sync(0xffffffffu, pu[kk][1], src2);
            uint32_t w2 = __shfl_sync(0xffffffffu, pu[kk][2], src2);
            uint32_t w3 = __shfl_sync(0xffffffffu, pu[kk][3], src2);
            pa[2] = sel ? w1 : w0;    // P[g][t4+4+8kk]
            pa[3] = sel ? w3 : w2;    // P[g+8][t4+4+8kk]
#pragma unroll
            for (int nt = 0; nt < 8; nt++) {
                uint32_t bf[2];
                bf[0] = Vs[(t4 + 8 * kk) * 72 + g + 8 * nt];
                bf[1] = Vs[(t4 + 4 + 8 * kk) * 72 + g + 8 * nt];
                mma_tf32(oacc[nt], pa, bf);
            }
        }
    }

    // epilogue: normalize, convert to tf32 bits, write g_att[b, t, h*64 + hs]
    const float inv0 = 1.0f / l0, inv1 = 1.0f / l1;
    const int b = bh >> 4;
    const int h = bh & (H_ - 1);
    const int qrow0 = q0 + wr + g;
    const int qrow1 = qrow0 + 8;
    uint32_t* dst0 = g_att + ((size_t)b * T_ + qrow0) * C_ + h * HS_;
    uint32_t* dst1 = g_att + ((size_t)b * T_ + qrow1) * C_ + h * HS_;
#pragma unroll
    for (int nt = 0; nt < 8; nt++) {
        uint2 v0 = {f2tf32(oacc[nt][0] * inv0), f2tf32(oacc[nt][1] * inv0)};
        *(uint2*)&dst0[8 * nt + 2 * t4] = v0;
        uint2 v1 = {f2tf32(oacc[nt][2] * inv1), f2tf32(oacc[nt][3] * inv1)};
        *(uint2*)&dst1[8 * nt + 2 * t4] = v1;
    }
}

// ---------------------------------------------------------------------------
extern "C" void kernel_launch(void* const* d_in, const int* in_sizes, int n_in,
                              void* d_out, int out_size)
{
    const float* x  = (const float*)d_in[0];
    const float* Wq = (const float*)d_in[1];
    const float* Wk = (const float*)d_in[2];
    const float* Wv = (const float*)d_in[3];
    const float* Wp = (const float*)d_in[4];
    const float* bp = (const float*)d_in[5];
    float* out = (float*)d_out;

    cudaFuncSetAttribute(qkv_gemm_mma, cudaFuncAttributeMaxDynamicSharedMemorySize,
                         GEMM_SMEM_BYTES);
    cudaFuncSetAttribute(out_gemm_mma, cudaFuncAttributeMaxDynamicSharedMemorySize,
                         GEMM_SMEM_BYTES);
    cudaFuncSetAttribute(flash_mma, cudaFuncAttributeMaxDynamicSharedMemorySize,
                         FA_SMEM_U32 * 4);

    // 0) one-time conversions: x -> tf32, weights -> K-major tf32
    convert_x<<<BT_ * C_ / 1024, 256>>>(x);
    transpose_w<<<dim3(C_ / 32, HS_ / 32, 3 * H_), dim3(32, 8)>>>(Wq, Wk, Wv);
    transpose_wp<<<dim3(C_ / 32, C_ / 32), dim3(32, 8)>>>(Wp);
    // 1) QKV projection (tensor, tf32, 3-stage cp.async, 2 CTA/SM)
    qkv_gemm_mma<<<dim3(3072 / 128, BT_ / 128), 256, GEMM_SMEM_BYTES>>>();
    // 2) Causal flash attention (R7 64-row, register P)
    flash_mma<<<dim3(T_ / 64, B_ * H_), 128, FA_SMEM_U32 * 4>>>();
    // 3) Output projection + bias (tensor, tf32, 3-stage cp.async, 2 CTA/SM)
    out_gemm_mma<<<dim3(C_ / 128, BT_ / 128), 256, GEMM_SMEM_BYTES>>>(bp, out);
}

// round 14
// speedup vs baseline: 1.1840x; 1.0344x over previous
#include <cuda_runtime.h>
#include <cstdint>

#define H_  16
#define HS_ 64
#define C_  1024
#define T_  2048
#define B_  2
#define BT_ (B_ * T_)   // 4096
#define LOG2E 1.4426950408889634f

// ---------------------------------------------------------------------------
// Scratch (no device allocation allowed)
// ---------------------------------------------------------------------------
__device__ uint32_t g_q[B_ * H_ * T_ * HS_];    // tf32 bits, pre-scaled
__device__ uint32_t g_k[B_ * H_ * T_ * HS_];    // tf32 bits
__device__ uint32_t g_v[B_ * H_ * T_ * HS_];    // tf32 bits
__device__ uint32_t g_att[BT_ * C_];            // tf32 bits (flash epilogue)
__device__ uint32_t g_xt[BT_ * C_];             // tf32 bits of x
__device__ uint32_t g_bt[3 * H_ * HS_ * C_];    // tf32 K-major QKV weights
__device__ uint32_t g_wpt[C_ * C_];             // tf32 K-major Wp

// ---------------------------------------------------------------------------
__device__ __forceinline__ uint32_t f2tf32(float f) {
    uint32_t r;
    asm("cvt.rna.tf32.f32 %0, %1;" : "=r"(r) : "f"(f));
    return r;
}
__device__ __forceinline__ float ex2f(float x) {
    float y;
    asm("ex2.approx.f32 %0, %1;" : "=f"(y) : "f"(x));
    return y;
}
__device__ __forceinline__ void mma_tf32(float c[4], const uint32_t a[4],
                                         const uint32_t b[2]) {
    asm volatile(
        "mma.sync.aligned.m16n8k8.row.col.f32.tf32.tf32.f32 "
        "{%0,%1,%2,%3}, {%4,%5,%6,%7}, {%8,%9}, {%0,%1,%2,%3};"
        : "+f"(c[0]), "+f"(c[1]), "+f"(c[2]), "+f"(c[3])
        : "r"(a[0]), "r"(a[1]), "r"(a[2]), "r"(a[3]), "r"(b[0]), "r"(b[1]));
}
__device__ __forceinline__ void cp_async16(void* dst, const void* src) {
    uint32_t d = (uint32_t)__cvta_generic_to_shared(dst);
    asm volatile("cp.async.cg.shared.global [%0], [%1], 16;"
                 :: "r"(d), "l"(src) : "memory");
}

// ---------------------------------------------------------------------------
// One-time input conversion: x -> tf32 bits
// ---------------------------------------------------------------------------
__global__ void convert_x(const float* __restrict__ x)
{
    const int i = (blockIdx.x * 256 + threadIdx.x) * 4;
    float4 v = *(const float4*)(x + i);
    uint4 t = {f2tf32(v.x), f2tf32(v.y), f2tf32(v.z), f2tf32(v.w)};
    *(uint4*)(g_xt + i) = t;
}

// ---------------------------------------------------------------------------
// Weight transposes into K-major tf32 scratch
// ---------------------------------------------------------------------------
__global__ void transpose_w(const float* __restrict__ Wq,
                            const float* __restrict__ Wk,
                            const float* __restrict__ Wv)
{
    __shared__ float tile[32][33];
    const int which = blockIdx.z >> 4;         // 0..2
    const int h     = blockIdx.z & 15;
    const float* W  = (which == 0) ? Wq : (which == 1) ? Wk : Wv;
    const int c0 = blockIdx.x * 32;
    const int d0 = blockIdx.y * 32;
    const int tx = threadIdx.x, ty = threadIdx.y;
#pragma unroll
    for (int j = 0; j < 32; j += 8)
        tile[ty + j][tx] = W[h * (C_ * HS_) + (c0 + ty + j) * HS_ + d0 + tx];
    __syncthreads();
    uint32_t* out = g_bt + (size_t)(which * 1024 + h * HS_ + d0) * C_ + c0;
#pragma unroll
    for (int j = 0; j < 32; j += 8)
        out[(ty + j) * C_ + tx] = f2tf32(tile[tx][ty + j]);
}

__global__ void transpose_wp(const float* __restrict__ Wp)
{
    __shared__ float tile[32][33];
    const int k0 = blockIdx.x * 32;
    const int n0 = blockIdx.y * 32;
    const int tx = threadIdx.x, ty = threadIdx.y;
#pragma unroll
    for (int j = 0; j < 32; j += 8)
        tile[ty + j][tx] = Wp[(k0 + ty + j) * C_ + n0 + tx];
    __syncthreads();
#pragma unroll
    for (int j = 0; j < 32; j += 8)
        g_wpt[(size_t)(n0 + ty + j) * C_ + k0 + tx] = f2tf32(tile[tx][ty + j]);
}

// ---------------------------------------------------------------------------
// tf32 mma.sync GEMM mainloop (R13, measured): 128x128 tile, 3-stage cp.async,
// 2 CTAs/SM.
// ---------------------------------------------------------------------------
#define NSTAGE   3
#define STG_U32  (2 * 128 * 36)
#define GEMM_SMEM_BYTES (NSTAGE * STG_U32 * 4)   // 110592

__device__ __forceinline__ void gemm_issue(uint32_t* gsm, int s,
                                           const uint32_t* Ap,
                                           const uint32_t* Bp,
                                           int k0, int lrow, int lc4)
{
    uint32_t* As = gsm + s * STG_U32;
    uint32_t* Bs = As + 128 * 36;
#pragma unroll
    for (int p = 0; p < 4; p++) {
        cp_async16(&As[(lrow + p * 32) * 36 + lc4], Ap + k0 + (size_t)p * 32 * C_);
        cp_async16(&Bs[(lrow + p * 32) * 36 + lc4], Bp + k0 + (size_t)p * 32 * C_);
    }
    asm volatile("cp.async.commit_group;" ::: "memory");
}

__device__ __forceinline__ void gemm_core(
    const uint32_t* __restrict__ A, const uint32_t* __restrict__ Bt,
    int m0, int n0, float acc[4][4][4], uint32_t* gsm)
{
    const int tid  = threadIdx.x;
    const int wid  = tid >> 5;
    const int lane = tid & 31;
    const int wm = (wid & 1) * 64;
    const int wn = (wid >> 1) * 32;
    const int g  = lane >> 2;
    const int t4 = lane & 3;

    const int lrow = tid >> 3;        // 0..31, + p*32
    const int lc4  = (tid & 7) * 4;   // k-col (u32)

    const uint32_t* Ap = A + (size_t)(m0 + lrow) * C_ + lc4;
    const uint32_t* Bp = Bt + (size_t)(n0 + lrow) * C_ + lc4;

#pragma unroll
    for (int mt = 0; mt < 4; mt++)
#pragma unroll
        for (int nt = 0; nt < 4; nt++)
#pragma unroll
            for (int i = 0; i < 4; i++) acc[mt][nt][i] = 0.f;

    gemm_issue(gsm, 0, Ap, Bp, 0,  lrow, lc4);
    gemm_issue(gsm, 1, Ap, Bp, 32, lrow, lc4);

#pragma unroll 1
    for (int it = 0; it < 32; ++it) {
        if (it < 31) asm volatile("cp.async.wait_group 1;" ::: "memory");
        else         asm volatile("cp.async.wait_group 0;" ::: "memory");
        __syncthreads();   // chunk `it` visible; buffer (it+2)%3 free

        if (it + 2 < 32)
            gemm_issue(gsm, (it + 2) % 3, Ap, Bp, (it + 2) * 32, lrow, lc4);

        const uint32_t* As = gsm + (it % 3) * STG_U32;
        const uint32_t* Bs = As + 128 * 36;
#pragma unroll
        for (int ks = 0; ks < 4; ks++) {
            const int k = ks * 8;
            uint32_t af[4][4], bf[4][2];
#pragma unroll
            for (int mt = 0; mt < 4; mt++) {
                const int r = wm + mt * 16 + g;
                af[mt][0] = As[r * 36 + k + t4];
                af[mt][1] = As[(r + 8) * 36 + k + t4];
                af[mt][2] = As[r * 36 + k + t4 + 4];
                af[mt][3] = As[(r + 8) * 36 + k + t4 + 4];
            }
#pragma unroll
            for (int nt = 0; nt < 4; nt++) {
                const int n = wn + nt * 8 + g;
                bf[nt][0] = Bs[n * 36 + k + t4];
                bf[nt][1] = Bs[n * 36 + k + t4 + 4];
            }
#pragma unroll
            for (int mt = 0; mt < 4; mt++)
#pragma unroll
                for (int nt = 0; nt < 4; nt++)
                    mma_tf32(acc[mt][nt], af[mt], bf[nt]);
        }
    }
}

// ---------------------------------------------------------------------------
// QKV projection: M=4096, N=3072, K=1024. Epilogue writes q/k/v as tf32 bits
// (q pre-scaled by 1/sqrt(HS)*log2e) so flash needs zero conversions.
// ---------------------------------------------------------------------------
__global__ __launch_bounds__(256, 2) void qkv_gemm_mma()
{
    extern __shared__ uint32_t gsm[];
    const int m0 = blockIdx.y * 128;
    const int n0 = blockIdx.x * 128;

    float acc[4][4][4];
    gemm_core(g_xt, g_bt, m0, n0, acc, gsm);

    const int tid  = threadIdx.x;
    const int wid  = tid >> 5;
    const int lane = tid & 31;
    const int wm = (wid & 1) * 64;
    const int wn = (wid >> 1) * 32;
    const int g  = lane >> 2;
    const int t4 = lane & 3;

#pragma unroll
    for (int mt = 0; mt < 4; mt++) {
#pragma unroll
        for (int nt = 0; nt < 4; nt++) {
            const int n  = n0 + wn + nt * 8 + t4 * 2;
            const int qk = n >> 10;
            const int h2 = (n >> 6) & (H_ - 1);
            const int d2 = n & (HS_ - 1);
            uint32_t* base = ((qk == 0) ? g_q : (qk == 1) ? g_k : g_v);
            const float sc = (qk == 0) ? (0.125f * LOG2E) : 1.0f;
#pragma unroll
            for (int half = 0; half < 2; half++) {
                const int m = m0 + wm + mt * 16 + g + half * 8;
                const int b = m >> 11;
                const int t = m & (T_ - 1);
                uint2 v;
                v.x = f2tf32(acc[mt][nt][half * 2 + 0] * sc);
                v.y = f2tf32(acc[mt][nt][half * 2 + 1] * sc);
                *(uint2*)&base[(((size_t)b * H_ + h2) * T_ + t) * HS_ + d2] = v;
            }
        }
    }
}

// ---------------------------------------------------------------------------
// Output projection: M=4096, N=1024, K=1024, + bias
// ---------------------------------------------------------------------------
__global__ __launch_bounds__(256, 2) void out_gemm_mma(const float* __restrict__ bp,
                                                       float* __restrict__ out)
{
    extern __shared__ uint32_t gsm[];
    const int m0 = blockIdx.y * 128;
    const int n0 = blockIdx.x * 128;

    float acc[4][4][4];
    gemm_core(g_att, g_wpt, m0, n0, acc, gsm);

    const int tid  = threadIdx.x;
    const int wid  = tid >> 5;
    const int lane = tid & 31;
    const int wm = (wid & 1) * 64;
    const int wn = (wid >> 1) * 32;
    const int g  = lane >> 2;
    const int t4 = lane & 3;

#pragma unroll
    for (int mt = 0; mt < 4; mt++) {
#pragma unroll
        for (int nt = 0; nt < 4; nt++) {
            const int n = n0 + wn + nt * 8 + t4 * 2;
            const float2 bias = *(const float2*)(bp + n);
#pragma unroll
            for (int half = 0; half < 2; half++) {
                const int m = m0 + wm + mt * 16 + g + half * 8;
                float2 v;
                v.x = acc[mt][nt][half * 2 + 0] + bias.x;
                v.y = acc[mt][nt][half * 2 + 1] + bias.y;
                *(float2*)&out[(size_t)m * C_ + n] = v;
            }
        }
    }
}

// ---------------------------------------------------------------------------
// Flash attention: tf32 mma.sync, register P, and now DOUBLE-BUFFERED cp.async
// K/V staging (operands pre-converted to tf32 by qkv's epilogue) — next tile's
// K/V transfer overlaps this tile's S/softmax/PV; zero cvt in the hot loop.
// ---------------------------------------------------------------------------
#define FA_KS_U32  (64 * 68)
#define FA_VS_U32  (64 * 72)
#define FA_BUF_U32 (FA_KS_U32 + FA_VS_U32)
#define FA_SMEM_U32 (2 * FA_BUF_U32)           // 71680 bytes

__device__ __forceinline__ void fa_issue(uint32_t* sm, int b,
                                         const uint32_t* kb,
                                         const uint32_t* vb,
                                         int k0, int tid)
{
    uint32_t* Ks = sm + b * FA_BUF_U32;
    uint32_t* Vs = Ks + FA_KS_U32;
#pragma unroll
    for (int it = 0; it < 8; it++) {
        int l = it * 128 + tid, r = l >> 4, c = (l & 15) * 4;
        cp_async16(&Ks[r * 68 + c], kb + (size_t)(k0 + r) * HS_ + c);
        cp_async16(&Vs[r * 72 + c], vb + (size_t)(k0 + r) * HS_ + c);
    }
    asm volatile("cp.async.commit_group;" ::: "memory");
}

__global__ __launch_bounds__(128, 3) void flash_mma()
{
    extern __shared__ uint32_t sm[];

    const int qt  = gridDim.x - 1 - blockIdx.x;   // long blocks first
    const int bh  = blockIdx.y;
    const int tid = threadIdx.x;
    const int wid = tid >> 5, lane = tid & 31;
    const int g = lane >> 2, t4 = lane & 3;
    const int wr = wid * 16;
    const int q0 = qt * 64;

    const uint32_t* qb = g_q + (size_t)bh * T_ * HS_;
    const uint32_t* kb = g_k + (size_t)bh * T_ * HS_;
    const uint32_t* vb = g_v + (size_t)bh * T_ * HS_;

    // stage Q (already tf32, pre-scaled) into buf1's Ks region
    uint32_t* Ks1 = sm + FA_BUF_U32;
#pragma unroll
    for (int it = 0; it < 8; it++) {
        int l = it * 128 + tid, r = l >> 4, c = (l & 15) * 4;
        *(uint4*)&Ks1[r * 68 + c] = *(const uint4*)(qb + (size_t)(q0 + r) * HS_ + c);
    }
    __syncthreads();

    uint32_t qa[8][4];
#pragma unroll
    for (int kk = 0; kk < 8; kk++) {
        qa[kk][0] = Ks1[(wr + g) * 68 + t4 + 8 * kk];
        qa[kk][1] = Ks1[(wr + g + 8) * 68 + t4 + 8 * kk];
        qa[kk][2] = Ks1[(wr + g) * 68 + t4 + 4 + 8 * kk];
        qa[kk][3] = Ks1[(wr + g + 8) * 68 + t4 + 4 + 8 * kk];
    }
    // (loop-top __syncthreads at kt=0 orders these reads before tile-1's
    //  cp.async overwrites buf1)

    // prologue: issue tile 0 into buf0
    fa_issue(sm, 0, kb, vb, 0, tid);

    float oacc[8][4];
#pragma unroll
    for (int nt = 0; nt < 8; nt++)
#pragma unroll
        for (int i = 0; i < 4; i++) oacc[nt][i] = 0.f;
    float m0 = -1e30f, m1 = -1e30f, l0 = 0.f, l1 = 0.f;

    // P shuffle mapping: P[g][t4+8kk] lives in lane g*4+(t4>>1), comp t4&1
    const int src0 = g * 4 + (t4 >> 1);
    const int src2 = src0 + 2;
    const bool sel = (t4 & 1) != 0;

#pragma unroll 1
    for (int kt = 0; kt <= qt; kt++) {
        __syncthreads();   // prior consumers of buf (kt+1)&1 are done
        const bool more = (kt + 1 <= qt);
        if (more)
            fa_issue(sm, (kt + 1) & 1, kb, vb, (kt + 1) * 64, tid);
        if (more) asm volatile("cp.async.wait_group 1;" ::: "memory");
        else      asm volatile("cp.async.wait_group 0;" ::: "memory");
        __syncthreads();   // tile kt visible to all warps

        const uint32_t* Ks = sm + (kt & 1) * FA_BUF_U32;
        const uint32_t* Vs = Ks + FA_KS_U32;

        // S = Q K^T  (units: log2)
        float sacc[8][4];
#pragma unroll
        for (int nt = 0; nt < 8; nt++)
#pragma unroll
            for (int i = 0; i < 4; i++) sacc[nt][i] = 0.f;
#pragma unroll
        for (int kk = 0; kk < 8; kk++) {
#pragma unroll
            for (int nt = 0; nt < 8; nt++) {
                uint32_t bf[2];
                bf[0] = Ks[(g + 8 * nt) * 68 + t4 + 8 * kk];
                bf[1] = Ks[(g + 8 * nt) * 68 + t4 + 4 + 8 * kk];
                mma_tf32(sacc[nt], qa[kk], bf);
            }
        }

        if (kt == qt) {   // causal mask on the diagonal tile (local coords)
            const int r0 = wr + g, r1 = wr + g + 8;
#pragma unroll
            for (int nt = 0; nt < 8; nt++) {
                const int c = 8 * nt + 2 * t4;
                if (c     > r0) sacc[nt][0] = -1e30f;
                if (c + 1 > r0) sacc[nt][1] = -1e30f;
                if (c     > r1) sacc[nt][2] = -1e30f;
                if (c + 1 > r1) sacc[nt][3] = -1e30f;
            }
        }

        // online softmax (base 2)
        float ml0 = -1e30f, ml1 = -1e30f;
#pragma unroll
        for (int nt = 0; nt < 8; nt++) {
            ml0 = fmaxf(ml0, fmaxf(sacc[nt][0], sacc[nt][1]));
            ml1 = fmaxf(ml1, fmaxf(sacc[nt][2], sacc[nt][3]));
        }
        ml0 = fmaxf(ml0, __shfl_xor_sync(0xffffffffu, ml0, 1));
        ml0 = fmaxf(ml0, __shfl_xor_sync(0xffffffffu, ml0, 2));
        ml1 = fmaxf(ml1, __shfl_xor_sync(0xffffffffu, ml1, 1));
        ml1 = fmaxf(ml1, __shfl_xor_sync(0xffffffffu, ml1, 2));
        const float mn0 = fmaxf(m0, ml0), mn1 = fmaxf(m1, ml1);
        const float corr0 = ex2f(m0 - mn0), corr1 = ex2f(m1 - mn1);
        m0 = mn0; m1 = mn1;

        uint32_t pu[8][4];
        float ps0 = 0.f, ps1 = 0.f;
#pragma unroll
        for (int nt = 0; nt < 8; nt++) {
            float p00 = ex2f(sacc[nt][0] - mn0);
            float p01 = ex2f(sacc[nt][1] - mn0);
            float p10 = ex2f(sacc[nt][2] - mn1);
            float p11 = ex2f(sacc[nt][3] - mn1);
            ps0 += p00 + p01;
            ps1 += p10 + p11;
            pu[nt][0] = f2tf32(p00); pu[nt][1] = f2tf32(p01);
            pu[nt][2] = f2tf32(p10); pu[nt][3] = f2tf32(p11);
            oacc[nt][0] *= corr0; oacc[nt][1] *= corr0;
            oacc[nt][2] *= corr1; oacc[nt][3] *= corr1;
        }
        ps0 += __shfl_xor_sync(0xffffffffu, ps0, 1);
        ps0 += __shfl_xor_sync(0xffffffffu, ps0, 2);
        ps1 += __shfl_xor_sync(0xffffffffu, ps1, 1);
        ps1 += __shfl_xor_sync(0xffffffffu, ps1, 2);
        l0 = l0 * corr0 + ps0;
        l1 = l1 * corr1 + ps1;

        // O += P V  (P redistributed C-frag -> A-frag via shuffles)
#pragma unroll
        for (int kk = 0; kk < 8; kk++) {
            uint32_t pa[4];
            uint32_t v0 = __shfl_sync(0xffffffffu, pu[kk][0], src0);
            uint32_t v1 = __shfl_sync(0xffffffffu, pu[kk][1], src0);
            uint32_t v2 = __shfl_sync(0xffffffffu, pu[kk][2], src0);
            uint32_t v3 = __shfl_sync(0xffffffffu, pu[kk][3], src0);
            pa[0] = sel ? v1 : v0;    // P[g][t4+8kk]
            pa[1] = sel ? v3 : v2;    // P[g+8][t4+8kk]
            uint32_t w0 = __shfl_sync(0xffffffffu, pu[kk][0], src2);
            uint32_t w1 = __shfl_sync(0xffffffffu, pu[kk][1], src2);
            uint32_t w2 = __shfl_sync(0xffffffffu, pu[kk][2], src2);
            uint32_t w3 = __shfl_sync(0xffffffffu, pu[kk][3], src2);
            pa[2] = sel ? w1 : w0;    // P[g][t4+4+8kk]
            pa[3] = sel ? w3 : w2;    // P[g+8][t4+4+8kk]
#pragma unroll
            for (int nt = 0; nt < 8; nt++) {
                uint32_t bf[2];
                bf[0] = Vs[(t4 + 8 * kk) * 72 + g + 8 * nt];
                bf[1] = Vs[(t4 + 4 + 8 * kk) * 72 + g + 8 * nt];
                mma_tf32(oacc[nt], pa, bf);
            }
        }
    }

    // epilogue: normalize, convert to tf32 bits, write g_att[b, t, h*64 + hs]
    const float inv0 = 1.0f / l0, inv1 = 1.0f / l1;
    const int b = bh >> 4;
    const int h = bh & (H_ - 1);
    const int qrow0 = q0 + wr + g;
    const int qrow1 = qrow0 + 8;
    uint32_t* dst0 = g_att + ((size_t)b * T_ + qrow0) * C_ + h * HS_;
    uint32_t* dst1 = g_att + ((size_t)b * T_ + qrow1) * C_ + h * HS_;
#pragma unroll
    for (int nt = 0; nt < 8; nt++) {
        uint2 v0 = {f2tf32(oacc[nt][0] * inv0), f2tf32(oacc[nt][1] * inv0)};
        *(uint2*)&dst0[8 * nt + 2 * t4] = v0;
        uint2 v1 = {f2tf32(oacc[nt][2] * inv1), f2tf32(oacc[nt][3] * inv1)};
        *(uint2*)&dst1[8 * nt + 2 * t4] = v1;
    }
}

// ---------------------------------------------------------------------------
extern "C" void kernel_launch(void* const* d_in, const int* in_sizes, int n_in,
                              void* d_out, int out_size)
{
    const float* x  = (const float*)d_in[0];
    const float* Wq = (const float*)d_in[1];
    const float* Wk = (const float*)d_in[2];
    const float* Wv = (const float*)d_in[3];
    const float* Wp = (const float*)d_in[4];
    const float* bp = (const float*)d_in[5];
    float* out = (float*)d_out;

    cudaFuncSetAttribute(qkv_gemm_mma, cudaFuncAttributeMaxDynamicSharedMemorySize,
                         GEMM_SMEM_BYTES);
    cudaFuncSetAttribute(out_gemm_mma, cudaFuncAttributeMaxDynamicSharedMemorySize,
                         GEMM_SMEM_BYTES);
    cudaFuncSetAttribute(flash_mma, cudaFuncAttributeMaxDynamicSharedMemorySize,
                         FA_SMEM_U32 * 4);

    // 0) one-time conversions: x -> tf32, weights -> K-major tf32
    convert_x<<<BT_ * C_ / 1024, 256>>>(x);
    transpose_w<<<dim3(C_ / 32, HS_ / 32, 3 * H_), dim3(32, 8)>>>(Wq, Wk, Wv);
    transpose_wp<<<dim3(C_ / 32, C_ / 32), dim3(32, 8)>>>(Wp);
    // 1) QKV projection (tensor, tf32, 3-stage cp.async, 2 CTA/SM)
    qkv_gemm_mma<<<dim3(3072 / 128, BT_ / 128), 256, GEMM_SMEM_BYTES>>>();
    // 2) Causal flash attention (register P, double-buffered cp.async K/V)
    flash_mma<<<dim3(T_ / 64, B_ * H_), 128, FA_SMEM_U32 * 4>>>();
    // 3) Output projection + bias (tensor, tf32, 3-stage cp.async, 2 CTA/SM)
    out_gemm_mma<<<dim3(C_ / 128, BT_ / 128), 256, GEMM_SMEM_BYTES>>>(bp, out);
}

// round 17
// speedup vs baseline: 1.2336x; 1.0419x over previous
#include <cuda_runtime.h>
#include <cstdint>

#define H_  16
#define HS_ 64
#define C_  1024
#define T_  2048
#define B_  2
#define BT_ (B_ * T_)   // 4096
#define LOG2E 1.4426950408889634f

// ---------------------------------------------------------------------------
// Scratch (no device allocation allowed)
// ---------------------------------------------------------------------------
__device__ uint32_t g_q[B_ * H_ * T_ * HS_];    // tf32 bits, pre-scaled
__device__ uint32_t g_k[B_ * H_ * T_ * HS_];    // tf32 bits
__device__ uint32_t g_v[B_ * H_ * T_ * HS_];    // tf32 bits
__device__ uint32_t g_att[BT_ * C_];            // tf32 bits (flash epilogue)
__device__ uint32_t g_xt[BT_ * C_];             // tf32 bits of x
__device__ uint32_t g_bt[3 * H_ * HS_ * C_];    // tf32 K-major QKV weights
__device__ uint32_t g_wpt[C_ * C_];             // tf32 K-major Wp

// ---------------------------------------------------------------------------
__device__ __forceinline__ uint32_t f2tf32(float f) {
    uint32_t r;
    asm("cvt.rna.tf32.f32 %0, %1;" : "=r"(r) : "f"(f));
    return r;
}
__device__ __forceinline__ float ex2f(float x) {
    float y;
    asm("ex2.approx.f32 %0, %1;" : "=f"(y) : "f"(x));
    return y;
}
__device__ __forceinline__ void mma_tf32(float c[4], const uint32_t a[4],
                                         const uint32_t b[2]) {
    asm volatile(
        "mma.sync.aligned.m16n8k8.row.col.f32.tf32.tf32.f32 "
        "{%0,%1,%2,%3}, {%4,%5,%6,%7}, {%8,%9}, {%0,%1,%2,%3};"
        : "+f"(c[0]), "+f"(c[1]), "+f"(c[2]), "+f"(c[3])
        : "r"(a[0]), "r"(a[1]), "r"(a[2]), "r"(a[3]), "r"(b[0]), "r"(b[1]));
}
__device__ __forceinline__ void cp_async16(void* dst, const void* src) {
    uint32_t d = (uint32_t)__cvta_generic_to_shared(dst);
    asm volatile("cp.async.cg.shared.global [%0], [%1], 16;"
                 :: "r"(d), "l"(src) : "memory");
}
__device__ __forceinline__ void ldm_x4(uint32_t r[4], uint32_t addr) {
    asm volatile(
        "ldmatrix.sync.aligned.m8n8.x4.shared.b16 {%0,%1,%2,%3}, [%4];"
        : "=r"(r[0]), "=r"(r[1]), "=r"(r[2]), "=r"(r[3]) : "r"(addr));
}

// ---------------------------------------------------------------------------
// One-time input conversion: x -> tf32 bits
// ---------------------------------------------------------------------------
__global__ void convert_x(const float* __restrict__ x)
{
    const int i = (blockIdx.x * 256 + threadIdx.x) * 4;
    float4 v = *(const float4*)(x + i);
    uint4 t = {f2tf32(v.x), f2tf32(v.y), f2tf32(v.z), f2tf32(v.w)};
    *(uint4*)(g_xt + i) = t;
}

// ---------------------------------------------------------------------------
// Weight transposes into K-major tf32 scratch
// ---------------------------------------------------------------------------
__global__ void transpose_w(const float* __restrict__ Wq,
                            const float* __restrict__ Wk,
                            const float* __restrict__ Wv)
{
    __shared__ float tile[32][33];
    const int which = blockIdx.z >> 4;         // 0..2
    const int h     = blockIdx.z & 15;
    const float* W  = (which == 0) ? Wq : (which == 1) ? Wk : Wv;
    const int c0 = blockIdx.x * 32;
    const int d0 = blockIdx.y * 32;
    const int tx = threadIdx.x, ty = threadIdx.y;
#pragma unroll
    for (int j = 0; j < 32; j += 8)
        tile[ty + j][tx] = W[h * (C_ * HS_) + (c0 + ty + j) * HS_ + d0 + tx];
    __syncthreads();
    uint32_t* out = g_bt + (size_t)(which * 1024 + h * HS_ + d0) * C_ + c0;
#pragma unroll
    for (int j = 0; j < 32; j += 8)
        out[(ty + j) * C_ + tx] = f2tf32(tile[tx][ty + j]);
}

__global__ void transpose_wp(const float* __restrict__ Wp)
{
    __shared__ float tile[32][33];
    const int k0 = blockIdx.x * 32;
    const int n0 = blockIdx.y * 32;
    const int tx = threadIdx.x, ty = threadIdx.y;
#pragma unroll
    for (int j = 0; j < 32; j += 8)
        tile[ty + j][tx] = Wp[(k0 + ty + j) * C_ + n0 + tx];
    __syncthreads();
#pragma unroll
    for (int j = 0; j < 32; j += 8)
        g_wpt[(size_t)(n0 + ty + j) * C_ + k0 + tx] = f2tf32(tile[tx][ty + j]);
}

// ---------------------------------------------------------------------------
// tf32 mma.sync GEMM mainloop: 128x128 tile, 3-stage cp.async, 2 CTAs/SM,
// fragment loads via ldmatrix.x4 (6 instructions/ks-step instead of 24 LDS)
// to unbind the LSU co-bottleneck (R14: 96 LDS vs 64 HMMA per chunk-warp).
// ---------------------------------------------------------------------------
#define NSTAGE   3
#define STG_U32  (2 * 128 * 36)
#define GEMM_SMEM_BYTES (NSTAGE * STG_U32 * 4)   // 110592

__device__ __forceinline__ void gemm_issue(uint32_t* gsm, int s,
                                           const uint32_t* Ap,
                                           const uint32_t* Bp,
                                           int k0, int lrow, int lc4)
{
    uint32_t* As = gsm + s * STG_U32;
    uint32_t* Bs = As + 128 * 36;
#pragma unroll
    for (int p = 0; p < 4; p++) {
        cp_async16(&As[(lrow + p * 32) * 36 + lc4], Ap + k0 + (size_t)p * 32 * C_);
        cp_async16(&Bs[(lrow + p * 32) * 36 + lc4], Bp + k0 + (size_t)p * 32 * C_);
    }
    asm volatile("cp.async.commit_group;" ::: "memory");
}

__device__ __forceinline__ void gemm_core(
    const uint32_t* __restrict__ A, const uint32_t* __restrict__ Bt,
    int m0, int n0, float acc[4][4][4], uint32_t* gsm)
{
    const int tid  = threadIdx.x;
    const int wid  = tid >> 5;
    const int lane = tid & 31;
    const int wm = (wid & 1) * 64;
    const int wn = (wid >> 1) * 32;

    // ldmatrix lane->address mapping
    // A (x4 per mt): matrices {rows r..r+7, k..k+3}, {r+8.., k..k+3},
    //                {r.., k+4..k+7}, {r+8.., k+4..k+7}
    const int arow = (lane & 7) + ((lane >> 3) & 1) * 8;
    const int acol = (lane >> 4) * 4;
    // B (x4 per nt-pair): {n..n+7, k..3}, {n.., k+4..7}, {n+8.., k..3}, {n+8.., k+4..7}
    const int brow = (lane & 7) + (lane >> 4) * 8;
    const int bcol = ((lane >> 3) & 1) * 4;

    const int lrow = tid >> 3;        // 0..31, + p*32
    const int lc4  = (tid & 7) * 4;   // k-col (u32)

    const uint32_t* Ap = A + (size_t)(m0 + lrow) * C_ + lc4;
    const uint32_t* Bp = Bt + (size_t)(n0 + lrow) * C_ + lc4;

    const uint32_t smem_base = (uint32_t)__cvta_generic_to_shared(gsm);

#pragma unroll
    for (int mt = 0; mt < 4; mt++)
#pragma unroll
        for (int nt = 0; nt < 4; nt++)
#pragma unroll
            for (int i = 0; i < 4; i++) acc[mt][nt][i] = 0.f;

    gemm_issue(gsm, 0, Ap, Bp, 0,  lrow, lc4);
    gemm_issue(gsm, 1, Ap, Bp, 32, lrow, lc4);

#pragma unroll 1
    for (int it = 0; it < 32; ++it) {
        if (it < 31) asm volatile("cp.async.wait_group 1;" ::: "memory");
        else         asm volatile("cp.async.wait_group 0;" ::: "memory");
        __syncthreads();   // chunk `it` visible; buffer (it+2)%3 free

        if (it + 2 < 32)
            gemm_issue(gsm, (it + 2) % 3, Ap, Bp, (it + 2) * 32, lrow, lc4);

        const uint32_t As_addr = smem_base + (uint32_t)((it % 3) * STG_U32) * 4;
        const uint32_t Bs_addr = As_addr + 128 * 36 * 4;
        const uint32_t a_base = As_addr + 4u * ((wm + arow) * 36 + acol);
        const uint32_t b_base = Bs_addr + 4u * ((wn + brow) * 36 + bcol);

#pragma unroll
        for (int ks = 0; ks < 4; ks++) {
            const uint32_t koff = 4u * (ks * 8);
            uint32_t af[4][4], bf[4][2];
#pragma unroll
            for (int mt = 0; mt < 4; mt++)
                ldm_x4(af[mt], a_base + koff + 4u * (mt * 16 * 36));
#pragma unroll
            for (int np = 0; np < 2; np++) {
                uint32_t r[4];
                ldm_x4(r, b_base + koff + 4u * (np * 16 * 36));
                bf[2 * np][0] = r[0];  bf[2 * np][1] = r[1];
                bf[2 * np + 1][0] = r[2];  bf[2 * np + 1][1] = r[3];
            }
#pragma unroll
            for (int mt = 0; mt < 4; mt++)
#pragma unroll
                for (int nt = 0; nt < 4; nt++)
                    mma_tf32(acc[mt][nt], af[mt], bf[nt]);
        }
    }
}

// ---------------------------------------------------------------------------
// QKV projection: M=4096, N=3072, K=1024. Epilogue writes q/k/v as tf32 bits
// (q pre-scaled by 1/sqrt(HS)*log2e) so flash needs zero conversions.
// ---------------------------------------------------------------------------
__global__ __launch_bounds__(256, 2) void qkv_gemm_mma()
{
    extern __shared__ uint32_t gsm[];
    const int m0 = blockIdx.y * 128;
    const int n0 = blockIdx.x * 128;

    float acc[4][4][4];
    gemm_core(g_xt, g_bt, m0, n0, acc, gsm);

    const int tid  = threadIdx.x;
    const int wid  = tid >> 5;
    const int lane = tid & 31;
    const int wm = (wid & 1) * 64;
    const int wn = (wid >> 1) * 32;
    const int g  = lane >> 2;
    const int t4 = lane & 3;

#pragma unroll
    for (int mt = 0; mt < 4; mt++) {
#pragma unroll
        for (int nt = 0; nt < 4; nt++) {
            const int n  = n0 + wn + nt * 8 + t4 * 2;
            const int qk = n >> 10;
            const int h2 = (n >> 6) & (H_ - 1);
            const int d2 = n & (HS_ - 1);
            uint32_t* base = ((qk == 0) ? g_q : (qk == 1) ? g_k : g_v);
            const float sc = (qk == 0) ? (0.125f * LOG2E) : 1.0f;
#pragma unroll
            for (int half = 0; half < 2; half++) {
                const int m = m0 + wm + mt * 16 + g + half * 8;
                const int b = m >> 11;
                const int t = m & (T_ - 1);
                uint2 v;
                v.x = f2tf32(acc[mt][nt][half * 2 + 0] * sc);
                v.y = f2tf32(acc[mt][nt][half * 2 + 1] * sc);
                *(uint2*)&base[(((size_t)b * H_ + h2) * T_ + t) * HS_ + d2] = v;
            }
        }
    }
}

// ---------------------------------------------------------------------------
// Output projection: M=4096, N=1024, K=1024, + bias
// ---------------------------------------------------------------------------
__global__ __launch_bounds__(256, 2) void out_gemm_mma(const float* __restrict__ bp,
                                                       float* __restrict__ out)
{
    extern __shared__ uint32_t gsm[];
    const int m0 = blockIdx.y * 128;
    const int n0 = blockIdx.x * 128;

    float acc[4][4][4];
    gemm_core(g_att, g_wpt, m0, n0, acc, gsm);

    const int tid  = threadIdx.x;
    const int wid  = tid >> 5;
    const int lane = tid & 31;
    const int wm = (wid & 1) * 64;
    const int wn = (wid >> 1) * 32;
    const int g  = lane >> 2;
    const int t4 = lane & 3;

#pragma unroll
    for (int mt = 0; mt < 4; mt++) {
#pragma unroll
        for (int nt = 0; nt < 4; nt++) {
            const int n = n0 + wn + nt * 8 + t4 * 2;
            const float2 bias = *(const float2*)(bp + n);
#pragma unroll
            for (int half = 0; half < 2; half++) {
                const int m = m0 + wm + mt * 16 + g + half * 8;
                float2 v;
                v.x = acc[mt][nt][half * 2 + 0] + bias.x;
                v.y = acc[mt][nt][half * 2 + 1] + bias.y;
                *(float2*)&out[(size_t)m * C_ + n] = v;
            }
        }
    }
}

// ---------------------------------------------------------------------------
// Flash attention (R14, measured): register P, double-buffered cp.async K/V,
// operands pre-converted tf32.
// ---------------------------------------------------------------------------
#define FA_KS_U32  (64 * 68)
#define FA_VS_U32  (64 * 72)
#define FA_BUF_U32 (FA_KS_U32 + FA_VS_U32)
#define FA_SMEM_U32 (2 * FA_BUF_U32)           // 71680 bytes

__device__ __forceinline__ void fa_issue(uint32_t* sm, int b,
                                         const uint32_t* kb,
                                         const uint32_t* vb,
                                         int k0, int tid)
{
    uint32_t* Ks = sm + b * FA_BUF_U32;
    uint32_t* Vs = Ks + FA_KS_U32;
#pragma unroll
    for (int it = 0; it < 8; it++) {
        int l = it * 128 + tid, r = l >> 4, c = (l & 15) * 4;
        cp_async16(&Ks[r * 68 + c], kb + (size_t)(k0 + r) * HS_ + c);
        cp_async16(&Vs[r * 72 + c], vb + (size_t)(k0 + r) * HS_ + c);
    }
    asm volatile("cp.async.commit_group;" ::: "memory");
}

__global__ __launch_bounds__(128, 3) void flash_mma()
{
    extern __shared__ uint32_t sm[];

    const int qt  = gridDim.x - 1 - blockIdx.x;   // long blocks first
    const int bh  = blockIdx.y;
    const int tid = threadIdx.x;
    const int wid = tid >> 5, lane = tid & 31;
    const int g = lane >> 2, t4 = lane & 3;
    const int wr = wid * 16;
    const int q0 = qt * 64;

    const uint32_t* qb = g_q + (size_t)bh * T_ * HS_;
    const uint32_t* kb = g_k + (size_t)bh * T_ * HS_;
    const uint32_t* vb = g_v + (size_t)bh * T_ * HS_;

    // stage Q (already tf32, pre-scaled) into buf1's Ks region
    uint32_t* Ks1 = sm + FA_BUF_U32;
#pragma unroll
    for (int it = 0; it < 8; it++) {
        int l = it * 128 + tid, r = l >> 4, c = (l & 15) * 4;
        *(uint4*)&Ks1[r * 68 + c] = *(const uint4*)(qb + (size_t)(q0 + r) * HS_ + c);
    }
    __syncthreads();

    uint32_t qa[8][4];
#pragma unroll
    for (int kk = 0; kk < 8; kk++) {
        qa[kk][0] = Ks1[(wr + g) * 68 + t4 + 8 * kk];
        qa[kk][1] = Ks1[(wr + g + 8) * 68 + t4 + 8 * kk];
        qa[kk][2] = Ks1[(wr + g) * 68 + t4 + 4 + 8 * kk];
        qa[kk][3] = Ks1[(wr + g + 8) * 68 + t4 + 4 + 8 * kk];
    }

    // prologue: issue tile 0 into buf0
    fa_issue(sm, 0, kb, vb, 0, tid);

    float oacc[8][4];
#pragma unroll
    for (int nt = 0; nt < 8; nt++)
#pragma unroll
        for (int i = 0; i < 4; i++) oacc[nt][i] = 0.f;
    float m0 = -1e30f, m1 = -1e30f, l0 = 0.f, l1 = 0.f;

    // P shuffle mapping: P[g][t4+8kk] lives in lane g*4+(t4>>1), comp t4&1
    const int src0 = g * 4 + (t4 >> 1);
    const int src2 = src0 + 2;
    const bool sel = (t4 & 1) != 0;

#pragma unroll 1
    for (int kt = 0; kt <= qt; kt++) {
        __syncthreads();   // prior consumers of buf (kt+1)&1 are done
        const bool more = (kt + 1 <= qt);
        if (more)
            fa_issue(sm, (kt + 1) & 1, kb, vb, (kt + 1) * 64, tid);
        if (more) asm volatile("cp.async.wait_group 1;" ::: "memory");
        else      asm volatile("cp.async.wait_group 0;" ::: "memory");
        __syncthreads();   // tile kt visible to all warps

        const uint32_t* Ks = sm + (kt & 1) * FA_BUF_U32;
        const uint32_t* Vs = Ks + FA_KS_U32;

        // S = Q K^T  (units: log2)
        float sacc[8][4];
#pragma unroll
        for (int nt = 0; nt < 8; nt++)
#pragma unroll
            for (int i = 0; i < 4; i++) sacc[nt][i] = 0.f;
#pragma unroll
        for (int kk = 0; kk < 8; kk++) {
#pragma unroll
            for (int nt = 0; nt < 8; nt++) {
                uint32_t bf[2];
                bf[0] = Ks[(g + 8 * nt) * 68 + t4 + 8 * kk];
                bf[1] = Ks[(g + 8 * nt) * 68 + t4 + 4 + 8 * kk];
                mma_tf32(sacc[nt], qa[kk], bf);
            }
        }

        if (kt == qt) {   // causal mask on the diagonal tile (local coords)
            const int r0 = wr + g, r1 = wr + g + 8;
#pragma unroll
            for (int nt = 0; nt < 8; nt++) {
                const int c = 8 * nt + 2 * t4;
                if (c     > r0) sacc[nt][0] = -1e30f;
                if (c + 1 > r0) sacc[nt][1] = -1e30f;
                if (c     > r1) sacc[nt][2] = -1e30f;
                if (c + 1 > r1) sacc[nt][3] = -1e30f;
            }
        }

        // online softmax (base 2)
        float ml0 = -1e30f, ml1 = -1e30f;
#pragma unroll
        for (int nt = 0; nt < 8; nt++) {
            ml0 = fmaxf(ml0, fmaxf(sacc[nt][0], sacc[nt][1]));
            ml1 = fmaxf(ml1, fmaxf(sacc[nt][2], sacc[nt][3]));
        }
        ml0 = fmaxf(ml0, __shfl_xor_sync(0xffffffffu, ml0, 1));
        ml0 = fmaxf(ml0, __shfl_xor_sync(0xffffffffu, ml0, 2));
        ml1 = fmaxf(ml1, __shfl_xor_sync(0xffffffffu, ml1, 1));
        ml1 = fmaxf(ml1, __shfl_xor_sync(0xffffffffu, ml1, 2));
        const float mn0 = fmaxf(m0, ml0), mn1 = fmaxf(m1, ml1);
        const float corr0 = ex2f(m0 - mn0), corr1 = ex2f(m1 - mn1);
        m0 = mn0; m1 = mn1;

        uint32_t pu[8][4];
        float ps0 = 0.f, ps1 = 0.f;
#pragma unroll
        for (int nt = 0; nt < 8; nt++) {
            float p00 = ex2f(sacc[nt][0] - mn0);
            float p01 = ex2f(sacc[nt][1] - mn0);
            float p10 = ex2f(sacc[nt][2] - mn1);
            float p11 = ex2f(sacc[nt][3] - mn1);
            ps0 += p00 + p01;
            ps1 += p10 + p11;
            pu[nt][0] = f2tf32(p00); pu[nt][1] = f2tf32(p01);
            pu[nt][2] = f2tf32(p10); pu[nt][3] = f2tf32(p11);
            oacc[nt][0] *= corr0; oacc[nt][1] *= corr0;
            oacc[nt][2] *= corr1; oacc[nt][3] *= corr1;
        }
        ps0 += __shfl_xor_sync(0xffffffffu, ps0, 1);
        ps0 += __shfl_xor_sync(0xffffffffu, ps0, 2);
        ps1 += __shfl_xor_sync(0xffffffffu, ps1, 1);
        ps1 += __shfl_xor_sync(0xffffffffu, ps1, 2);
        l0 = l0 * corr0 + ps0;
        l1 = l1 * corr1 + ps1;

        // O += P V  (P redistributed C-frag -> A-frag via shuffles)
#pragma unroll
        for (int kk = 0; kk < 8; kk++) {
            uint32_t pa[4];
            uint32_t v0 = __shfl_sync(0xffffffffu, pu[kk][0], src0);
            uint32_t v1 = __shfl_sync(0xffffffffu, pu[kk][1], src0);
            uint32_t v2 = __shfl_sync(0xffffffffu, pu[kk][2], src0);
            uint32_t v3 = __shfl_sync(0xffffffffu, pu[kk][3], src0);
            pa[0] = sel ? v1 : v0;    // P[g][t4+8kk]
            pa[1] = sel ? v3 : v2;    // P[g+8][t4+8kk]
            uint32_t w0 = __shfl_sync(0xffffffffu, pu[kk][0], src2);
            uint32_t w1 = __shfl_sync(0xffffffffu, pu[kk][1], src2);
            uint32_t w2 = __shfl_sync(0xffffffffu, pu[kk][2], src2);
            uint32_t w3 = __shfl_sync(0xffffffffu, pu[kk][3], src2);
            pa[2] = sel ? w1 : w0;    // P[g][t4+4+8kk]
            pa[3] = sel ? w3 : w2;    // P[g+8][t4+4+8kk]
#pragma unroll
            for (int nt = 0; nt < 8; nt++) {
                uint32_t bf[2];
                bf[0] = Vs[(t4 + 8 * kk) * 72 + g + 8 * nt];
                bf[1] = Vs[(t4 + 4 + 8 * kk) * 72 + g + 8 * nt];
                mma_tf32(oacc[nt], pa, bf);
            }
        }
    }

    // epilogue: normalize, convert to tf32 bits, write g_att[b, t, h*64 + hs]
    const float inv0 = 1.0f / l0, inv1 = 1.0f / l1;
    const int b = bh >> 4;
    const int h = bh & (H_ - 1);
    const int qrow0 = q0 + wr + g;
    const int qrow1 = qrow0 + 8;
    uint32_t* dst0 = g_att + ((size_t)b * T_ + qrow0) * C_ + h * HS_;
    uint32_t* dst1 = g_att + ((size_t)b * T_ + qrow1) * C_ + h * HS_;
#pragma unroll
    for (int nt = 0; nt < 8; nt++) {
        uint2 v0 = {f2tf32(oacc[nt][0] * inv0), f2tf32(oacc[nt][1] * inv0)};
        *(uint2*)&dst0[8 * nt + 2 * t4] = v0;
        uint2 v1 = {f2tf32(oacc[nt][2] * inv1), f2tf32(oacc[nt][3] * inv1)};
        *(uint2*)&dst1[8 * nt + 2 * t4] = v1;
    }
}

// ---------------------------------------------------------------------------
extern "C" void kernel_launch(void* const* d_in, const int* in_sizes, int n_in,
                              void* d_out, int out_size)
{
    const float* x  = (const float*)d_in[0];
    const float* Wq = (const float*)d_in[1];
    const float* Wk = (const float*)d_in[2];
    const float* Wv = (const float*)d_in[3];
    const float* Wp = (const float*)d_in[4];
    const float* bp = (const float*)d_in[5];
    float* out = (float*)d_out;

    cudaFuncSetAttribute(qkv_gemm_mma, cudaFuncAttributeMaxDynamicSharedMemorySize,
                         GEMM_SMEM_BYTES);
    cudaFuncSetAttribute(out_gemm_mma, cudaFuncAttributeMaxDynamicSharedMemorySize,
                         GEMM_SMEM_BYTES);
    cudaFuncSetAttribute(flash_mma, cudaFuncAttributeMaxDynamicSharedMemorySize,
                         FA_SMEM_U32 * 4);

    // 0) one-time conversions: x -> tf32, weights -> K-major tf32
    convert_x<<<BT_ * C_ / 1024, 256>>>(x);
    transpose_w<<<dim3(C_ / 32, HS_ / 32, 3 * H_), dim3(32, 8)>>>(Wq, Wk, Wv);
    transpose_wp<<<dim3(C_ / 32, C_ / 32), dim3(32, 8)>>>(Wp);
    // 1) QKV projection (tensor, tf32, cp.async + ldmatrix)
    qkv_gemm_mma<<<dim3(3072 / 128, BT_ / 128), 256, GEMM_SMEM_BYTES>>>();
    // 2) Causal flash attention (register P, double-buffered cp.async K/V)
    flash_mma<<<dim3(T_ / 64, B_ * H_), 128, FA_SMEM_U32 * 4>>>();
    // 3) Output projection + bias (tensor, tf32, cp.async + ldmatrix)
    out_gemm_mma<<<dim3(C_ / 128, BT_ / 128), 256, GEMM_SMEM_BYTES>>>(bp, out);
}